// round 9
// baseline (speedup 1.0000x reference)
#include <cuda_runtime.h>
#include <stdint.h>
#include <math.h>

#define N_NODES 50000
#define N_EDGES 800000
#define EP      (N_EDGES + N_NODES)   // edges incl. self-loops = 850000
#define DIM     256
#define NH      8
#define NC      32
#define NBLK    ((N_NODES + 255) / 256)   // 196 scan blocks
#define WELEMS  (DIM * DIM)               // 65536

// ---------------- static device scratch (no allocs allowed) ----------------
__device__ __align__(16) float g_xl [(size_t)N_NODES * DIM];   // x @ Wl
__device__ __align__(16) float g_xr [(size_t)N_NODES * DIM];   // x @ Wr
__device__ __align__(16) float g_h  [(size_t)N_NODES * DIM];   // layer-1 out (tf32-rounded)
__device__ __align__(16) float g_xc [(size_t)N_NODES * DIM];   // x, tf32-rounded
__device__ __align__(16) float g_wc [4 * WELEMS];              // Wl1,Wr1,Wl2,Wr2 tf32-rounded
__device__ int g_deg [N_NODES];
__device__ int g_roff[N_NODES + 1];
__device__ int g_cur [N_NODES];
__device__ int g_csr [EP];
__device__ int g_part[256];
__device__ int g_pofs[256];
__device__ int g_is64;

// ---------------- tf32 helpers ----------------
__device__ __forceinline__ unsigned f2tf(float x) {
    unsigned r;
    asm("cvt.rna.tf32.f32 %0, %1;" : "=r"(r) : "f"(x));
    return r;
}
__device__ __forceinline__ float f2tf_f(float x) { return __uint_as_float(f2tf(x)); }

// ---------------- edge index dtype detection ----------------
__global__ void detect_kernel(const int* __restrict__ e) {
    int zeros = 0;
#pragma unroll
    for (int i = 1; i < 128; i += 2) zeros += (e[i] == 0);
    g_is64 = (zeros >= 32);
}

__device__ __forceinline__ int load_idx(const void* e, size_t i) {
    return g_is64 ? (int)((const long long*)e)[i] : ((const int*)e)[i];
}

// ---------------- input conversion to tf32 (RNA, stored as fp32 bits) ------
__global__ void convx_kernel(const float* __restrict__ x) {
    int i = blockIdx.x * blockDim.x + threadIdx.x;   // float4 index
    if (i >= N_NODES * DIM / 4) return;
    float4 v = ((const float4*)x)[i];
    ((float4*)g_xc)[i] = make_float4(f2tf_f(v.x), f2tf_f(v.y), f2tf_f(v.z), f2tf_f(v.w));
}

__global__ void convw_kernel(const float* __restrict__ Wl1, const float* __restrict__ Wr1,
                             const float* __restrict__ Wl2, const float* __restrict__ Wr2) {
    int i = blockIdx.x * blockDim.x + threadIdx.x;   // float4 index, 16384 total
    if (i >= WELEMS / 4) return;
    const float* src[4] = {Wl1, Wr1, Wl2, Wr2};
#pragma unroll
    for (int m = 0; m < 4; m++) {
        float4 v = ((const float4*)src[m])[i];
        ((float4*)(g_wc + m * WELEMS))[i] =
            make_float4(f2tf_f(v.x), f2tf_f(v.y), f2tf_f(v.z), f2tf_f(v.w));
    }
}

// ---------------- CSR build ----------------
__global__ void deg_init_kernel() {
    int i = blockIdx.x * blockDim.x + threadIdx.x;
    if (i < N_NODES) g_deg[i] = 1;
}

__global__ void hist_kernel(const void* __restrict__ eidx) {
    int e = blockIdx.x * blockDim.x + threadIdx.x;
    if (e < N_EDGES) atomicAdd(&g_deg[load_idx(eidx, (size_t)N_EDGES + e)], 1);
}

__global__ void scan1_kernel() {
    __shared__ int sh[256];
    int t = threadIdx.x;
    int i = blockIdx.x * 256 + t;
    int v = (i < N_NODES) ? g_deg[i] : 0;
    sh[t] = v;
    __syncthreads();
#pragma unroll
    for (int off = 1; off < 256; off <<= 1) {
        int u = (t >= off) ? sh[t - off] : 0;
        __syncthreads();
        sh[t] += u;
        __syncthreads();
    }
    if (i < N_NODES) g_roff[i] = sh[t] - v;
    if (t == 255) g_part[blockIdx.x] = sh[255];
}

__global__ void scan2_kernel() {
    __shared__ int sh[256];
    int t = threadIdx.x;
    int v = (t < NBLK) ? g_part[t] : 0;
    sh[t] = v;
    __syncthreads();
#pragma unroll
    for (int off = 1; off < 256; off <<= 1) {
        int u = (t >= off) ? sh[t - off] : 0;
        __syncthreads();
        sh[t] += u;
        __syncthreads();
    }
    g_pofs[t] = sh[t] - v;
}

__global__ void scan3_kernel() {
    int i = blockIdx.x * 256 + threadIdx.x;
    if (i < N_NODES) {
        int val = g_roff[i] + g_pofs[blockIdx.x];
        g_roff[i] = val;
        g_cur[i]  = val;
    }
    if (i == 0) g_roff[N_NODES] = EP;
}

__global__ void scatter_kernel(const void* __restrict__ eidx) {
    int e = blockIdx.x * blockDim.x + threadIdx.x;
    if (e >= EP) return;
    int src, dst;
    if (e < N_EDGES) { src = load_idx(eidx, e); dst = load_idx(eidx, (size_t)N_EDGES + e); }
    else             { src = e - N_EDGES;       dst = src; }
    int pos = atomicAdd(&g_cur[dst], 1);
    g_csr[pos] = src;
}

// ---------------- tf32 GEMM: cp.async pipeline, pre-converted operands -----
#define TBM 128
#define TBN 128
#define TBK 32
#define XS_STRIDE 36
#define WS_STRIDE 136
#define XS_SZ (TBM * XS_STRIDE)                   // 4608 words
#define WS_SZ (TBK * WS_STRIDE)                   // 4352 words
#define STAGE_W (XS_SZ + WS_SZ)                   // 8960 words = 35840 B
#define GEMM_SMEM_BYTES (3 * STAGE_W * 4)         // 107520 B

__device__ __forceinline__ void cp16(uint32_t dst, const void* src) {
    asm volatile("cp.async.ca.shared.global [%0], [%1], 16;"
                 :: "r"(dst), "l"(src));
}
__device__ __forceinline__ void cp16z(uint32_t dst, const void* src, bool valid) {
    int sz = valid ? 16 : 0;
    asm volatile("cp.async.ca.shared.global [%0], [%1], 16, %2;"
                 :: "r"(dst), "l"(src), "r"(sz));
}
__device__ __forceinline__ void cp_commit() {
    asm volatile("cp.async.commit_group;" ::: "memory");
}
__device__ __forceinline__ void cp_wait1() {
    asm volatile("cp.async.wait_group 1;" ::: "memory");
}

__device__ __forceinline__ void mma_tf32(float* d,
                                         unsigned a0, unsigned a1,
                                         unsigned a2, unsigned a3,
                                         unsigned b0, unsigned b1) {
    asm volatile(
        "mma.sync.aligned.m16n8k8.row.col.f32.tf32.tf32.f32 "
        "{%0,%1,%2,%3}, {%4,%5,%6,%7}, {%8,%9}, {%0,%1,%2,%3};"
        : "+f"(d[0]), "+f"(d[1]), "+f"(d[2]), "+f"(d[3])
        : "r"(a0), "r"(a1), "r"(a2), "r"(a3), "r"(b0), "r"(b1));
}

__global__ __launch_bounds__(256, 2)
void gemm_tf32_kernel(int layer) {
    extern __shared__ unsigned smem_u[];

    const float* X = (layer == 0) ? g_xc : g_h;
    const float* W = g_wc + (size_t)(layer * 2 + blockIdx.z) * WELEMS;
    float*      Cout = (blockIdx.z == 0) ? g_xl : g_xr;

    int m0 = blockIdx.x * TBM;
    int n0 = blockIdx.y * TBN;
    int tid = threadIdx.x;
    int wid = tid >> 5, lane = tid & 31;
    int warp_m = wid & 1;
    int warp_n = wid >> 1;
    int g4 = lane >> 2;
    int t4 = lane & 3;

    int xrow[4], xkc[4], wkr[4], wnc[4];
    uint32_t xoff[4], woff[4];
    uint32_t sb = (uint32_t)__cvta_generic_to_shared(smem_u);
#pragma unroll
    for (int t = 0; t < 4; t++) {
        int f = tid + t * 256;
        xrow[t] = f >> 3;  xkc[t] = (f & 7) << 2;
        wkr[t]  = f >> 5;  wnc[t] = (f & 31) << 2;
        xoff[t] = (uint32_t)(xrow[t] * XS_STRIDE + xkc[t]) * 4;
        woff[t] = (uint32_t)(XS_SZ + wkr[t] * WS_STRIDE + wnc[t]) * 4;
    }

    auto issue_tile = [&](int tile, int stage) {
        int k0 = tile * TBK;
        uint32_t base = sb + (uint32_t)stage * (STAGE_W * 4);
#pragma unroll
        for (int t = 0; t < 4; t++) {
            int gr = m0 + xrow[t];
            bool v = gr < N_NODES;
            int grc = v ? gr : 0;
            cp16z(base + xoff[t], X + (size_t)grc * DIM + k0 + xkc[t], v);
            cp16 (base + woff[t], W + (size_t)(k0 + wkr[t]) * DIM + n0 + wnc[t]);
        }
    };

    float acc[4][4][4];
#pragma unroll
    for (int mt = 0; mt < 4; mt++)
#pragma unroll
        for (int nt = 0; nt < 4; nt++)
#pragma unroll
            for (int r = 0; r < 4; r++) acc[mt][nt][r] = 0.f;

    const int NK = DIM / TBK;   // 8

    issue_tile(0, 0);
    cp_commit();
    issue_tile(1, 1);
    cp_commit();

    for (int i = 0; i < NK; i++) {
        cp_wait1();
        __syncthreads();   // tile i resident; previous compute done CTA-wide

        if (i + 2 < NK) issue_tile(i + 2, (i + 2) % 3);
        cp_commit();

        unsigned* Xs = smem_u + (i % 3) * STAGE_W;
        unsigned* Ws = Xs + XS_SZ;

#pragma unroll
        for (int ks = 0; ks < 4; ks++) {
            unsigned b[4][2];
#pragma unroll
            for (int nt = 0; nt < 4; nt++) {
                int col = warp_n * 32 + nt * 8 + g4;
                b[nt][0] = Ws[(ks * 8 +     t4) * WS_STRIDE + col];
                b[nt][1] = Ws[(ks * 8 + 4 + t4) * WS_STRIDE + col];
            }
#pragma unroll
            for (int mt = 0; mt < 4; mt++) {
                int row = warp_m * 64 + mt * 16 + g4;
                unsigned a0 = Xs[ row      * XS_STRIDE + ks * 8 +     t4];
                unsigned a1 = Xs[(row + 8) * XS_STRIDE + ks * 8 +     t4];
                unsigned a2 = Xs[ row      * XS_STRIDE + ks * 8 + 4 + t4];
                unsigned a3 = Xs[(row + 8) * XS_STRIDE + ks * 8 + 4 + t4];
#pragma unroll
                for (int nt = 0; nt < 4; nt++)
                    mma_tf32(acc[mt][nt], a0, a1, a2, a3, b[nt][0], b[nt][1]);
            }
        }
    }

#pragma unroll
    for (int mt = 0; mt < 4; mt++) {
        int r0 = m0 + warp_m * 64 + mt * 16 + g4;
#pragma unroll
        for (int nt = 0; nt < 4; nt++) {
            int c = n0 + warp_n * 32 + nt * 8 + t4 * 2;
            if (r0 < N_NODES)
                *(float2*)(Cout + (size_t)r0 * DIM + c) =
                    make_float2(acc[mt][nt][0], acc[mt][nt][1]);
            if (r0 + 8 < N_NODES)
                *(float2*)(Cout + (size_t)(r0 + 8) * DIM + c) =
                    make_float2(acc[mt][nt][2], acc[mt][nt][3]);
        }
    }
}

// ---------------- fused GATv2 node kernel (warp per dst node) --------------
__device__ __forceinline__ float dot4_lrelu(float4 a, float4 l, float4 r) {
    float z, s;
    z = l.x + r.x; z = z > 0.f ? z : 0.2f * z; s  = a.x * z;
    z = l.y + r.y; z = z > 0.f ? z : 0.2f * z; s += a.y * z;
    z = l.z + r.z; z = z > 0.f ? z : 0.2f * z; s += a.z * z;
    z = l.w + r.w; z = z > 0.f ? z : 0.2f * z; s += a.w * z;
    return s;
}

#define WPB 8   // warps per block

__global__ __launch_bounds__(WPB * 32)
void gat_node_kernel(const float* __restrict__ att,
                     const float* __restrict__ bias,
                     float* __restrict__ outp, int mode) {
    int node = blockIdx.x * WPB + (threadIdx.x >> 5);
    if (node >= N_NODES) return;
    int lane = threadIdx.x & 31;
    int grp  = lane >> 3;
    int sub  = lane & 7;

    const float4* pa = (const float4*)att;
    float4 a0 = pa[lane], a1 = pa[lane + 32];
    const float4* pr = (const float4*)(g_xr + (size_t)node * DIM);
    float4 r0 = pr[lane], r1 = pr[lane + 32];

    int beg = g_roff[node], end = g_roff[node + 1];

    float4 acc0 = make_float4(0.f, 0.f, 0.f, 0.f);
    float4 acc1 = make_float4(0.f, 0.f, 0.f, 0.f);
    float  s0 = 0.f, s1 = 0.f;

    const float4* pl = (const float4*)(g_xl + (size_t)g_csr[beg] * DIM);
    float4 nl0 = pl[lane], nl1 = pl[lane + 32];

    for (int e = beg; e < end; e++) {
        float4 l0 = nl0, l1 = nl1;
        if (e + 1 < end) {
            const float4* pn = (const float4*)(g_xl + (size_t)g_csr[e + 1] * DIM);
            nl0 = pn[lane]; nl1 = pn[lane + 32];
        }

        float sl = dot4_lrelu(a0, l0, r0);
        float sh = dot4_lrelu(a1, l1, r1);
#pragma unroll
        for (int off = 4; off; off >>= 1) {
            sl += __shfl_xor_sync(0xffffffffu, sl, off);
            sh += __shfl_xor_sync(0xffffffffu, sh, off);
        }
        float ex = 0.f;
        if (sub < 2) ex = __expf(sub == 0 ? sl : sh);
        float exl = __shfl_sync(0xffffffffu, ex, grp * 8);
        float exh = __shfl_sync(0xffffffffu, ex, grp * 8 + 1);

        acc0.x += exl * l0.x; acc0.y += exl * l0.y;
        acc0.z += exl * l0.z; acc0.w += exl * l0.w;
        acc1.x += exh * l1.x; acc1.y += exh * l1.y;
        acc1.z += exh * l1.z; acc1.w += exh * l1.w;
        s0 += exl; s1 += exh;
    }

    float inv0 = 1.f / s0, inv1 = 1.f / s1;
    const float4* pb = (const float4*)bias;
    float4 b0 = pb[lane], b1 = pb[lane + 32];

    float4 v0 = make_float4(acc0.x * inv0 + b0.x, acc0.y * inv0 + b0.y,
                            acc0.z * inv0 + b0.z, acc0.w * inv0 + b0.w);
    float4 v1 = make_float4(acc1.x * inv1 + b1.x, acc1.y * inv1 + b1.y,
                            acc1.z * inv1 + b1.z, acc1.w * inv1 + b1.w);

    if (mode == 0) {   // ELU + tf32-round -> layer-2 GEMM input
        v0.x = f2tf_f(v0.x > 0.f ? v0.x : expm1f(v0.x));
        v0.y = f2tf_f(v0.y > 0.f ? v0.y : expm1f(v0.y));
        v0.z = f2tf_f(v0.z > 0.f ? v0.z : expm1f(v0.z));
        v0.w = f2tf_f(v0.w > 0.f ? v0.w : expm1f(v0.w));
        v1.x = f2tf_f(v1.x > 0.f ? v1.x : expm1f(v1.x));
        v1.y = f2tf_f(v1.y > 0.f ? v1.y : expm1f(v1.y));
        v1.z = f2tf_f(v1.z > 0.f ? v1.z : expm1f(v1.z));
        v1.w = f2tf_f(v1.w > 0.f ? v1.w : expm1f(v1.w));
        float4* po = (float4*)(g_h + (size_t)node * DIM);
        po[lane]      = v0;
        po[lane + 32] = v1;
    } else {
        float4* po = (float4*)(outp + (size_t)node * DIM);
        po[lane]      = v0;
        po[lane + 32] = v1;
    }
}

// ---------------- host entry ----------------
extern "C" void kernel_launch(void* const* d_in, const int* in_sizes, int n_in,
                              void* d_out, int out_size) {
    const float* x    = (const float*)d_in[0];
    const void*  eidx = d_in[1];
    const float* Wl1  = (const float*)d_in[2];
    const float* Wr1  = (const float*)d_in[3];
    const float* att1 = (const float*)d_in[4];
    const float* b1   = (const float*)d_in[5];
    const float* Wl2  = (const float*)d_in[6];
    const float* Wr2  = (const float*)d_in[7];
    const float* att2 = (const float*)d_in[8];
    const float* b2   = (const float*)d_in[9];
    float*       outp = (float*)d_out;

    cudaFuncSetAttribute(gemm_tf32_kernel,
                         cudaFuncAttributeMaxDynamicSharedMemorySize,
                         GEMM_SMEM_BYTES);

    dim3 ggemm((N_NODES + TBM - 1) / TBM, DIM / TBN, 2);
    dim3 gnode((N_NODES + WPB - 1) / WPB);

    // ---- operand conversion + CSR build ----
    detect_kernel  <<<1, 1>>>((const int*)eidx);
    convx_kernel   <<<(N_NODES * DIM / 4 + 255) / 256, 256>>>(x);
    convw_kernel   <<<(WELEMS / 4 + 255) / 256, 256>>>(Wl1, Wr1, Wl2, Wr2);
    deg_init_kernel<<<NBLK, 256>>>();
    hist_kernel    <<<(N_EDGES + 255) / 256, 256>>>(eidx);
    scan1_kernel   <<<NBLK, 256>>>();
    scan2_kernel   <<<1, 256>>>();
    scan3_kernel   <<<NBLK, 256>>>();
    scatter_kernel <<<(EP + 255) / 256, 256>>>(eidx);

    // ---- layer 1 ----
    gemm_tf32_kernel<<<ggemm, 256, GEMM_SMEM_BYTES>>>(0);
    gat_node_kernel <<<gnode, WPB * 32>>>(att1, b1, outp, 0);

    // ---- layer 2 ----
    gemm_tf32_kernel<<<ggemm, 256, GEMM_SMEM_BYTES>>>(1);
    gat_node_kernel <<<gnode, WPB * 32>>>(att2, b2, outp, 1);
}

// round 10
// speedup vs baseline: 1.1904x; 1.1904x over previous
#include <cuda_runtime.h>
#include <cuda_fp16.h>
#include <stdint.h>
#include <math.h>

#define N_NODES 50000
#define N_EDGES 800000
#define EP      (N_EDGES + N_NODES)   // edges incl. self-loops = 850000
#define DIM     256
#define NH      8
#define NC      32
#define NBLK    ((N_NODES + 255) / 256)   // 196 scan blocks

// ---------------- static device scratch (no allocs allowed) ----------------
__device__ __align__(16) float g_xl [(size_t)N_NODES * DIM];   // x @ Wl
__device__ __align__(16) float g_xr [(size_t)N_NODES * DIM];   // x @ Wr
__device__ __align__(16) float g_h  [(size_t)N_NODES * DIM];   // layer-1 out after ELU
__device__ int g_deg [N_NODES];
__device__ int g_roff[N_NODES + 1];
__device__ int g_cur [N_NODES];
__device__ int g_csr [EP];
__device__ int g_part[256];
__device__ int g_pofs[256];
__device__ int g_is64;

// ---------------- edge index dtype detection ----------------
__global__ void detect_kernel(const int* __restrict__ e) {
    int zeros = 0;
#pragma unroll
    for (int i = 1; i < 128; i += 2) zeros += (e[i] == 0);
    g_is64 = (zeros >= 32);
}

__device__ __forceinline__ int load_idx(const void* e, size_t i) {
    return g_is64 ? (int)((const long long*)e)[i] : ((const int*)e)[i];
}

// ---------------- CSR build ----------------
__global__ void deg_init_kernel() {
    int i = blockIdx.x * blockDim.x + threadIdx.x;
    if (i < N_NODES) g_deg[i] = 1;
}

__global__ void hist_kernel(const void* __restrict__ eidx) {
    int e = blockIdx.x * blockDim.x + threadIdx.x;
    if (e < N_EDGES) atomicAdd(&g_deg[load_idx(eidx, (size_t)N_EDGES + e)], 1);
}

__global__ void scan1_kernel() {
    __shared__ int sh[256];
    int t = threadIdx.x;
    int i = blockIdx.x * 256 + t;
    int v = (i < N_NODES) ? g_deg[i] : 0;
    sh[t] = v;
    __syncthreads();
#pragma unroll
    for (int off = 1; off < 256; off <<= 1) {
        int u = (t >= off) ? sh[t - off] : 0;
        __syncthreads();
        sh[t] += u;
        __syncthreads();
    }
    if (i < N_NODES) g_roff[i] = sh[t] - v;
    if (t == 255) g_part[blockIdx.x] = sh[255];
}

__global__ void scan2_kernel() {
    __shared__ int sh[256];
    int t = threadIdx.x;
    int v = (t < NBLK) ? g_part[t] : 0;
    sh[t] = v;
    __syncthreads();
#pragma unroll
    for (int off = 1; off < 256; off <<= 1) {
        int u = (t >= off) ? sh[t - off] : 0;
        __syncthreads();
        sh[t] += u;
        __syncthreads();
    }
    g_pofs[t] = sh[t] - v;
}

__global__ void scan3_kernel() {
    int i = blockIdx.x * 256 + threadIdx.x;
    if (i < N_NODES) {
        int val = g_roff[i] + g_pofs[blockIdx.x];
        g_roff[i] = val;
        g_cur[i]  = val;
    }
    if (i == 0) g_roff[N_NODES] = EP;
}

__global__ void scatter_kernel(const void* __restrict__ eidx) {
    int e = blockIdx.x * blockDim.x + threadIdx.x;
    if (e >= EP) return;
    int src, dst;
    if (e < N_EDGES) { src = load_idx(eidx, e); dst = load_idx(eidx, (size_t)N_EDGES + e); }
    else             { src = e - N_EDGES;       dst = src; }
    int pos = atomicAdd(&g_cur[dst], 1);
    g_csr[pos] = src;
}

// ---------------- fp16 tensor-core GEMM: C[M,256] = X[M,256] @ W[256,256] ---
// 128x128 block tile, BK=32, 8 warps (2x4) each 64x32 via m16n8k16.f16.f32.
// fp32 -> half2 conversion at the staging step (RN, same 10-bit mantissa as
// tf32). Double-buffered static smem + register prefetch.
// Xs layout: half2 (row, kpair), stride 20 uints -> conflict-free A LDS.
// Ws layout: half2 {k,k+1} per column n: (kpair, n), stride 136 -> c-f B LDS.
#define TBM 128
#define TBN 128
#define TBK 32
#define XH_STRIDE 20
#define WH_STRIDE 136
#define XH_SZ (TBM * XH_STRIDE)    // 2560 uints
#define WH_SZ ((TBK / 2) * WH_STRIDE)   // 2176 uints

__device__ __forceinline__ unsigned h2u(float a, float b) {
    __half2 h = __floats2half2_rn(a, b);
    return *(unsigned*)&h;
}

__device__ __forceinline__ void mma_f16(float* d,
                                        unsigned a0, unsigned a1,
                                        unsigned a2, unsigned a3,
                                        unsigned b0, unsigned b1) {
    asm volatile(
        "mma.sync.aligned.m16n8k16.row.col.f32.f16.f16.f32 "
        "{%0,%1,%2,%3}, {%4,%5,%6,%7}, {%8,%9}, {%0,%1,%2,%3};"
        : "+f"(d[0]), "+f"(d[1]), "+f"(d[2]), "+f"(d[3])
        : "r"(a0), "r"(a1), "r"(a2), "r"(a3), "r"(b0), "r"(b1));
}

__global__ __launch_bounds__(256, 2)
void gemm_f16_kernel(const float* __restrict__ Xin,
                     const float* __restrict__ Wl,
                     const float* __restrict__ Wr,
                     int use_h) {
    __shared__ unsigned Xs2[2][XH_SZ];   // 2 x 10240 B
    __shared__ unsigned Ws2[2][WH_SZ];   // 2 x  8704 B

    const float* X   = use_h ? g_h : Xin;
    const float* W   = (blockIdx.z == 0) ? Wl : Wr;
    float*      Cout = (blockIdx.z == 0) ? g_xl : g_xr;

    int m0 = blockIdx.x * TBM;
    int n0 = blockIdx.y * TBN;
    int tid = threadIdx.x;
    int wid = tid >> 5, lane = tid & 31;
    int warp_m = wid & 1;      // 2 warps over M (64 rows)
    int warp_n = wid >> 1;     // 4 warps over N (32 cols)
    int g4 = lane >> 2;        // 0..7
    int t4 = lane & 3;         // 0..3

    // X staging: 4 float4 per thread: row = f>>3 (0..127), k4 = (f&7)*4
    int xrow[4], xk4[4];
    // W staging: 2 groups per thread: kpair = idx>>5 (0..15), n4 = (idx&31)*4
    int wkp[2], wn4[2];
#pragma unroll
    for (int t = 0; t < 4; t++) {
        int f = tid + t * 256;
        xrow[t] = f >> 3;  xk4[t] = (f & 7) << 2;
    }
#pragma unroll
    for (int t = 0; t < 2; t++) {
        int idx = tid + t * 256;
        wkp[t] = idx >> 5;  wn4[t] = (idx & 31) << 2;
    }

    float4 xv[4], wva[2], wvb[2];

    auto load_tile = [&](int k0) {
#pragma unroll
        for (int t = 0; t < 4; t++) {
            int gr = m0 + xrow[t];
            xv[t] = make_float4(0.f, 0.f, 0.f, 0.f);
            if (gr < N_NODES)
                xv[t] = *(const float4*)(X + (size_t)gr * DIM + k0 + xk4[t]);
        }
#pragma unroll
        for (int t = 0; t < 2; t++) {
            int kr = k0 + 2 * wkp[t];
            wva[t] = *(const float4*)(W + (size_t)kr       * DIM + n0 + wn4[t]);
            wvb[t] = *(const float4*)(W + (size_t)(kr + 1) * DIM + n0 + wn4[t]);
        }
    };

    auto store_tile = [&](int p) {
        unsigned* Xs = Xs2[p];
        unsigned* Ws = Ws2[p];
#pragma unroll
        for (int t = 0; t < 4; t++) {
            uint2 u;
            u.x = h2u(xv[t].x, xv[t].y);
            u.y = h2u(xv[t].z, xv[t].w);
            *(uint2*)&Xs[xrow[t] * XH_STRIDE + (xk4[t] >> 1)] = u;
        }
#pragma unroll
        for (int t = 0; t < 2; t++) {
            uint4 u;
            u.x = h2u(wva[t].x, wvb[t].x);
            u.y = h2u(wva[t].y, wvb[t].y);
            u.z = h2u(wva[t].z, wvb[t].z);
            u.w = h2u(wva[t].w, wvb[t].w);
            *(uint4*)&Ws[wkp[t] * WH_STRIDE + wn4[t]] = u;
        }
    };

    float acc[4][4][4];
#pragma unroll
    for (int mt = 0; mt < 4; mt++)
#pragma unroll
        for (int nt = 0; nt < 4; nt++)
#pragma unroll
            for (int r = 0; r < 4; r++) acc[mt][nt][r] = 0.f;

    // prologue
    load_tile(0);
    store_tile(0);
    __syncthreads();
    load_tile(TBK);

    int p = 0;
    for (int k0 = 0; k0 < DIM; k0 += TBK) {
        unsigned* Xs = Xs2[p];
        unsigned* Ws = Ws2[p];

#pragma unroll
        for (int ks = 0; ks < 2; ks++) {   // 2 x k16 slices per 32-k tile
            unsigned b[4][2];
#pragma unroll
            for (int nt = 0; nt < 4; nt++) {
                int col = warp_n * 32 + nt * 8 + g4;
                b[nt][0] = Ws[(ks * 8 +     t4) * WH_STRIDE + col];
                b[nt][1] = Ws[(ks * 8 + 4 + t4) * WH_STRIDE + col];
            }
#pragma unroll
            for (int mt = 0; mt < 4; mt++) {
                int row = warp_m * 64 + mt * 16 + g4;
                unsigned a0 = Xs[ row      * XH_STRIDE + ks * 8 +     t4];
                unsigned a1 = Xs[(row + 8) * XH_STRIDE + ks * 8 +     t4];
                unsigned a2 = Xs[ row      * XH_STRIDE + ks * 8 + 4 + t4];
                unsigned a3 = Xs[(row + 8) * XH_STRIDE + ks * 8 + 4 + t4];
#pragma unroll
                for (int nt = 0; nt < 4; nt++)
                    mma_f16(acc[mt][nt], a0, a1, a2, a3, b[nt][0], b[nt][1]);
            }
        }

        if (k0 + TBK < DIM) {
            store_tile(1 - p);                            // stage k0+TBK
            if (k0 + 2 * TBK < DIM) load_tile(k0 + 2 * TBK);  // prefetch
            __syncthreads();
        }
        p ^= 1;
    }

#pragma unroll
    for (int mt = 0; mt < 4; mt++) {
        int r0 = m0 + warp_m * 64 + mt * 16 + g4;
#pragma unroll
        for (int nt = 0; nt < 4; nt++) {
            int c = n0 + warp_n * 32 + nt * 8 + t4 * 2;
            if (r0 < N_NODES)
                *(float2*)(Cout + (size_t)r0 * DIM + c) =
                    make_float2(acc[mt][nt][0], acc[mt][nt][1]);
            if (r0 + 8 < N_NODES)
                *(float2*)(Cout + (size_t)(r0 + 8) * DIM + c) =
                    make_float2(acc[mt][nt][2], acc[mt][nt][3]);
        }
    }
}

// ---------------- fused GATv2 node kernel (warp per dst node) --------------
__device__ __forceinline__ float dot4_lrelu(float4 a, float4 l, float4 r) {
    float z, s;
    z = l.x + r.x; z = z > 0.f ? z : 0.2f * z; s  = a.x * z;
    z = l.y + r.y; z = z > 0.f ? z : 0.2f * z; s += a.y * z;
    z = l.z + r.z; z = z > 0.f ? z : 0.2f * z; s += a.z * z;
    z = l.w + r.w; z = z > 0.f ? z : 0.2f * z; s += a.w * z;
    return s;
}

#define WPB 8   // warps per block

__global__ __launch_bounds__(WPB * 32)
void gat_node_kernel(const float* __restrict__ att,
                     const float* __restrict__ bias,
                     float* __restrict__ outp, int mode) {
    int node = blockIdx.x * WPB + (threadIdx.x >> 5);
    if (node >= N_NODES) return;
    int lane = threadIdx.x & 31;
    int grp  = lane >> 3;
    int sub  = lane & 7;

    const float4* pa = (const float4*)att;
    float4 a0 = pa[lane], a1 = pa[lane + 32];
    const float4* pr = (const float4*)(g_xr + (size_t)node * DIM);
    float4 r0 = pr[lane], r1 = pr[lane + 32];

    int beg = g_roff[node], end = g_roff[node + 1];

    float4 acc0 = make_float4(0.f, 0.f, 0.f, 0.f);
    float4 acc1 = make_float4(0.f, 0.f, 0.f, 0.f);
    float  s0 = 0.f, s1 = 0.f;

    const float4* pl = (const float4*)(g_xl + (size_t)g_csr[beg] * DIM);
    float4 nl0 = pl[lane], nl1 = pl[lane + 32];

    for (int e = beg; e < end; e++) {
        float4 l0 = nl0, l1 = nl1;
        if (e + 1 < end) {
            const float4* pn = (const float4*)(g_xl + (size_t)g_csr[e + 1] * DIM);
            nl0 = pn[lane]; nl1 = pn[lane + 32];
        }

        float sl = dot4_lrelu(a0, l0, r0);
        float sh = dot4_lrelu(a1, l1, r1);
#pragma unroll
        for (int off = 4; off; off >>= 1) {
            sl += __shfl_xor_sync(0xffffffffu, sl, off);
            sh += __shfl_xor_sync(0xffffffffu, sh, off);
        }
        float ex = 0.f;
        if (sub < 2) ex = __expf(sub == 0 ? sl : sh);
        float exl = __shfl_sync(0xffffffffu, ex, grp * 8);
        float exh = __shfl_sync(0xffffffffu, ex, grp * 8 + 1);

        acc0.x += exl * l0.x; acc0.y += exl * l0.y;
        acc0.z += exl * l0.z; acc0.w += exl * l0.w;
        acc1.x += exh * l1.x; acc1.y += exh * l1.y;
        acc1.z += exh * l1.z; acc1.w += exh * l1.w;
        s0 += exl; s1 += exh;
    }

    float inv0 = 1.f / s0, inv1 = 1.f / s1;
    const float4* pb = (const float4*)bias;
    float4 b0 = pb[lane], b1 = pb[lane + 32];

    float4 v0 = make_float4(acc0.x * inv0 + b0.x, acc0.y * inv0 + b0.y,
                            acc0.z * inv0 + b0.z, acc0.w * inv0 + b0.w);
    float4 v1 = make_float4(acc1.x * inv1 + b1.x, acc1.y * inv1 + b1.y,
                            acc1.z * inv1 + b1.z, acc1.w * inv1 + b1.w);

    float* dst = (mode == 0) ? g_h : outp;
    if (mode == 0) {   // ELU -> layer-2 GEMM input
        v0.x = v0.x > 0.f ? v0.x : expm1f(v0.x);
        v0.y = v0.y > 0.f ? v0.y : expm1f(v0.y);
        v0.z = v0.z > 0.f ? v0.z : expm1f(v0.z);
        v0.w = v0.w > 0.f ? v0.w : expm1f(v0.w);
        v1.x = v1.x > 0.f ? v1.x : expm1f(v1.x);
        v1.y = v1.y > 0.f ? v1.y : expm1f(v1.y);
        v1.z = v1.z > 0.f ? v1.z : expm1f(v1.z);
        v1.w = v1.w > 0.f ? v1.w : expm1f(v1.w);
    }
    float4* po = (float4*)(dst + (size_t)node * DIM);
    po[lane]      = v0;
    po[lane + 32] = v1;
}

// ---------------- host entry ----------------
extern "C" void kernel_launch(void* const* d_in, const int* in_sizes, int n_in,
                              void* d_out, int out_size) {
    const float* x    = (const float*)d_in[0];
    const void*  eidx = d_in[1];
    const float* Wl1  = (const float*)d_in[2];
    const float* Wr1  = (const float*)d_in[3];
    const float* att1 = (const float*)d_in[4];
    const float* b1   = (const float*)d_in[5];
    const float* Wl2  = (const float*)d_in[6];
    const float* Wr2  = (const float*)d_in[7];
    const float* att2 = (const float*)d_in[8];
    const float* b2   = (const float*)d_in[9];
    float*       outp = (float*)d_out;

    dim3 ggemm((N_NODES + TBM - 1) / TBM, DIM / TBN, 2);
    dim3 gnode((N_NODES + WPB - 1) / WPB);

    // ---- CSR build (once, reused by both layers) ----
    detect_kernel  <<<1, 1>>>((const int*)eidx);
    deg_init_kernel<<<NBLK, 256>>>();
    hist_kernel    <<<(N_EDGES + 255) / 256, 256>>>(eidx);
    scan1_kernel   <<<NBLK, 256>>>();
    scan2_kernel   <<<1, 256>>>();
    scan3_kernel   <<<NBLK, 256>>>();
    scatter_kernel <<<(EP + 255) / 256, 256>>>(eidx);

    // ---- layer 1 ----
    gemm_f16_kernel<<<ggemm, 256>>>(x, Wl1, Wr1, 0);
    gat_node_kernel<<<gnode, WPB * 32>>>(att1, b1, outp, 0);

    // ---- layer 2 ----
    gemm_f16_kernel<<<ggemm, 256>>>(x, Wl2, Wr2, 1);
    gat_node_kernel<<<gnode, WPB * 32>>>(att2, b2, outp, 1);
}

// round 11
// speedup vs baseline: 1.2766x; 1.0725x over previous
#include <cuda_runtime.h>
#include <cuda_fp16.h>
#include <stdint.h>
#include <math.h>

#define N_NODES 50000
#define N_EDGES 800000
#define EP      (N_EDGES + N_NODES)   // edges incl. self-loops = 850000
#define DIM     256
#define NH      8
#define NC      32
#define NBLK    ((N_NODES + 255) / 256)   // 196 scan blocks

// ---------------- static device scratch (no allocs allowed) ----------------
__device__ __align__(16) unsigned g_xlh[(size_t)N_NODES * DIM / 2]; // x @ Wl, half2-packed
__device__ __align__(16) float g_xr [(size_t)N_NODES * DIM];        // x @ Wr (fp32)
__device__ __align__(16) float g_h  [(size_t)N_NODES * DIM];        // layer-1 out after ELU
__device__ int g_deg [N_NODES];
__device__ int g_roff[N_NODES + 1];
__device__ int g_cur [N_NODES];
__device__ int g_csr [EP];
__device__ int g_part[256];
__device__ int g_pofs[256];
__device__ int g_is64;

// ---------------- edge index dtype detection ----------------
__global__ void detect_kernel(const int* __restrict__ e) {
    int zeros = 0;
#pragma unroll
    for (int i = 1; i < 128; i += 2) zeros += (e[i] == 0);
    g_is64 = (zeros >= 32);
}

__device__ __forceinline__ int load_idx(const void* e, size_t i) {
    return g_is64 ? (int)((const long long*)e)[i] : ((const int*)e)[i];
}

// ---------------- CSR build ----------------
__global__ void deg_init_kernel() {
    int i = blockIdx.x * blockDim.x + threadIdx.x;
    if (i < N_NODES) g_deg[i] = 1;
}

__global__ void hist_kernel(const void* __restrict__ eidx) {
    int e = blockIdx.x * blockDim.x + threadIdx.x;
    if (e < N_EDGES) atomicAdd(&g_deg[load_idx(eidx, (size_t)N_EDGES + e)], 1);
}

__global__ void scan1_kernel() {
    __shared__ int sh[256];
    int t = threadIdx.x;
    int i = blockIdx.x * 256 + t;
    int v = (i < N_NODES) ? g_deg[i] : 0;
    sh[t] = v;
    __syncthreads();
#pragma unroll
    for (int off = 1; off < 256; off <<= 1) {
        int u = (t >= off) ? sh[t - off] : 0;
        __syncthreads();
        sh[t] += u;
        __syncthreads();
    }
    if (i < N_NODES) g_roff[i] = sh[t] - v;
    if (t == 255) g_part[blockIdx.x] = sh[255];
}

__global__ void scan2_kernel() {
    __shared__ int sh[256];
    int t = threadIdx.x;
    int v = (t < NBLK) ? g_part[t] : 0;
    sh[t] = v;
    __syncthreads();
#pragma unroll
    for (int off = 1; off < 256; off <<= 1) {
        int u = (t >= off) ? sh[t - off] : 0;
        __syncthreads();
        sh[t] += u;
        __syncthreads();
    }
    g_pofs[t] = sh[t] - v;
}

__global__ void scan3_kernel() {
    int i = blockIdx.x * 256 + threadIdx.x;
    if (i < N_NODES) {
        int val = g_roff[i] + g_pofs[blockIdx.x];
        g_roff[i] = val;
        g_cur[i]  = val;
    }
    if (i == 0) g_roff[N_NODES] = EP;
}

__global__ void scatter_kernel(const void* __restrict__ eidx) {
    int e = blockIdx.x * blockDim.x + threadIdx.x;
    if (e >= EP) return;
    int src, dst;
    if (e < N_EDGES) { src = load_idx(eidx, e); dst = load_idx(eidx, (size_t)N_EDGES + e); }
    else             { src = e - N_EDGES;       dst = src; }
    int pos = atomicAdd(&g_cur[dst], 1);
    g_csr[pos] = src;
}

// ---------------- fp16 tensor-core GEMM: C[M,256] = X[M,256] @ W[256,256] ---
// 128x128 block tile, BK=32, 8 warps (2x4) each 64x32 via m16n8k16.f16.f32.
// xl output stored half2-packed; xr output fp32.
#define TBM 128
#define TBN 128
#define TBK 32
#define XH_STRIDE 20
#define WH_STRIDE 136
#define XH_SZ (TBM * XH_STRIDE)         // 2560 uints
#define WH_SZ ((TBK / 2) * WH_STRIDE)   // 2176 uints

__device__ __forceinline__ unsigned h2u(float a, float b) {
    __half2 h = __floats2half2_rn(a, b);
    return *(unsigned*)&h;
}

__device__ __forceinline__ void mma_f16(float* d,
                                        unsigned a0, unsigned a1,
                                        unsigned a2, unsigned a3,
                                        unsigned b0, unsigned b1) {
    asm volatile(
        "mma.sync.aligned.m16n8k16.row.col.f32.f16.f16.f32 "
        "{%0,%1,%2,%3}, {%4,%5,%6,%7}, {%8,%9}, {%0,%1,%2,%3};"
        : "+f"(d[0]), "+f"(d[1]), "+f"(d[2]), "+f"(d[3])
        : "r"(a0), "r"(a1), "r"(a2), "r"(a3), "r"(b0), "r"(b1));
}

__global__ __launch_bounds__(256, 2)
void gemm_f16_kernel(const float* __restrict__ Xin,
                     const float* __restrict__ Wl,
                     const float* __restrict__ Wr,
                     int use_h) {
    __shared__ unsigned Xs2[2][XH_SZ];
    __shared__ unsigned Ws2[2][WH_SZ];

    const float* X = use_h ? g_h : Xin;
    const float* W = (blockIdx.z == 0) ? Wl : Wr;

    int m0 = blockIdx.x * TBM;
    int n0 = blockIdx.y * TBN;
    int tid = threadIdx.x;
    int wid = tid >> 5, lane = tid & 31;
    int warp_m = wid & 1;
    int warp_n = wid >> 1;
    int g4 = lane >> 2;
    int t4 = lane & 3;

    int xrow[4], xk4[4];
    int wkp[2], wn4[2];
#pragma unroll
    for (int t = 0; t < 4; t++) {
        int f = tid + t * 256;
        xrow[t] = f >> 3;  xk4[t] = (f & 7) << 2;
    }
#pragma unroll
    for (int t = 0; t < 2; t++) {
        int idx = tid + t * 256;
        wkp[t] = idx >> 5;  wn4[t] = (idx & 31) << 2;
    }

    float4 xv[4], wva[2], wvb[2];

    auto load_tile = [&](int k0) {
#pragma unroll
        for (int t = 0; t < 4; t++) {
            int gr = m0 + xrow[t];
            xv[t] = make_float4(0.f, 0.f, 0.f, 0.f);
            if (gr < N_NODES)
                xv[t] = *(const float4*)(X + (size_t)gr * DIM + k0 + xk4[t]);
        }
#pragma unroll
        for (int t = 0; t < 2; t++) {
            int kr = k0 + 2 * wkp[t];
            wva[t] = *(const float4*)(W + (size_t)kr       * DIM + n0 + wn4[t]);
            wvb[t] = *(const float4*)(W + (size_t)(kr + 1) * DIM + n0 + wn4[t]);
        }
    };

    auto store_tile = [&](int p) {
        unsigned* Xs = Xs2[p];
        unsigned* Ws = Ws2[p];
#pragma unroll
        for (int t = 0; t < 4; t++) {
            uint2 u;
            u.x = h2u(xv[t].x, xv[t].y);
            u.y = h2u(xv[t].z, xv[t].w);
            *(uint2*)&Xs[xrow[t] * XH_STRIDE + (xk4[t] >> 1)] = u;
        }
#pragma unroll
        for (int t = 0; t < 2; t++) {
            uint4 u;
            u.x = h2u(wva[t].x, wvb[t].x);
            u.y = h2u(wva[t].y, wvb[t].y);
            u.z = h2u(wva[t].z, wvb[t].z);
            u.w = h2u(wva[t].w, wvb[t].w);
            *(uint4*)&Ws[wkp[t] * WH_STRIDE + wn4[t]] = u;
        }
    };

    float acc[4][4][4];
#pragma unroll
    for (int mt = 0; mt < 4; mt++)
#pragma unroll
        for (int nt = 0; nt < 4; nt++)
#pragma unroll
            for (int r = 0; r < 4; r++) acc[mt][nt][r] = 0.f;

    load_tile(0);
    store_tile(0);
    __syncthreads();
    load_tile(TBK);

    int p = 0;
    for (int k0 = 0; k0 < DIM; k0 += TBK) {
        unsigned* Xs = Xs2[p];
        unsigned* Ws = Ws2[p];

#pragma unroll
        for (int ks = 0; ks < 2; ks++) {
            unsigned b[4][2];
#pragma unroll
            for (int nt = 0; nt < 4; nt++) {
                int col = warp_n * 32 + nt * 8 + g4;
                b[nt][0] = Ws[(ks * 8 +     t4) * WH_STRIDE + col];
                b[nt][1] = Ws[(ks * 8 + 4 + t4) * WH_STRIDE + col];
            }
#pragma unroll
            for (int mt = 0; mt < 4; mt++) {
                int row = warp_m * 64 + mt * 16 + g4;
                unsigned a0 = Xs[ row      * XH_STRIDE + ks * 8 +     t4];
                unsigned a1 = Xs[(row + 8) * XH_STRIDE + ks * 8 +     t4];
                unsigned a2 = Xs[ row      * XH_STRIDE + ks * 8 + 4 + t4];
                unsigned a3 = Xs[(row + 8) * XH_STRIDE + ks * 8 + 4 + t4];
#pragma unroll
                for (int nt = 0; nt < 4; nt++)
                    mma_f16(acc[mt][nt], a0, a1, a2, a3, b[nt][0], b[nt][1]);
            }
        }

        if (k0 + TBK < DIM) {
            store_tile(1 - p);
            if (k0 + 2 * TBK < DIM) load_tile(k0 + 2 * TBK);
            __syncthreads();
        }
        p ^= 1;
    }

    if (blockIdx.z == 0) {
        // xl: half2-packed output
#pragma unroll
        for (int mt = 0; mt < 4; mt++) {
            int r0 = m0 + warp_m * 64 + mt * 16 + g4;
#pragma unroll
            for (int nt = 0; nt < 4; nt++) {
                int c = n0 + warp_n * 32 + nt * 8 + t4 * 2;
                if (r0 < N_NODES)
                    g_xlh[((size_t)r0 * DIM + c) >> 1] =
                        h2u(acc[mt][nt][0], acc[mt][nt][1]);
                if (r0 + 8 < N_NODES)
                    g_xlh[((size_t)(r0 + 8) * DIM + c) >> 1] =
                        h2u(acc[mt][nt][2], acc[mt][nt][3]);
            }
        }
    } else {
        // xr: fp32 output
#pragma unroll
        for (int mt = 0; mt < 4; mt++) {
            int r0 = m0 + warp_m * 64 + mt * 16 + g4;
#pragma unroll
            for (int nt = 0; nt < 4; nt++) {
                int c = n0 + warp_n * 32 + nt * 8 + t4 * 2;
                if (r0 < N_NODES)
                    *(float2*)(g_xr + (size_t)r0 * DIM + c) =
                        make_float2(acc[mt][nt][0], acc[mt][nt][1]);
                if (r0 + 8 < N_NODES)
                    *(float2*)(g_xr + (size_t)(r0 + 8) * DIM + c) =
                        make_float2(acc[mt][nt][2], acc[mt][nt][3]);
            }
        }
    }
}

// ---------------- fused GATv2 node kernel (warp per dst node) --------------
__device__ __forceinline__ float dot4_lrelu(float4 a, float4 l, float4 r) {
    float z, s;
    z = l.x + r.x; z = z > 0.f ? z : 0.2f * z; s  = a.x * z;
    z = l.y + r.y; z = z > 0.f ? z : 0.2f * z; s += a.y * z;
    z = l.z + r.z; z = z > 0.f ? z : 0.2f * z; s += a.z * z;
    z = l.w + r.w; z = z > 0.f ? z : 0.2f * z; s += a.w * z;
    return s;
}

__device__ __forceinline__ float4 u2f4(uint2 u) {
    float2 lo = __half22float2(*(__half2*)&u.x);
    float2 hi = __half22float2(*(__half2*)&u.y);
    return make_float4(lo.x, lo.y, hi.x, hi.y);
}

#define WPB 8   // warps per block

__global__ __launch_bounds__(WPB * 32)
void gat_node_kernel(const float* __restrict__ att,
                     const float* __restrict__ bias,
                     float* __restrict__ outp, int mode) {
    int node = blockIdx.x * WPB + (threadIdx.x >> 5);
    if (node >= N_NODES) return;
    int lane = threadIdx.x & 31;
    int grp  = lane >> 3;
    int sub  = lane & 7;

    const float4* pa = (const float4*)att;
    float4 a0 = pa[lane], a1 = pa[lane + 32];
    const float4* pr = (const float4*)(g_xr + (size_t)node * DIM);
    float4 r0 = pr[lane], r1 = pr[lane + 32];

    int beg = g_roff[node], end = g_roff[node + 1];

    float4 acc0 = make_float4(0.f, 0.f, 0.f, 0.f);
    float4 acc1 = make_float4(0.f, 0.f, 0.f, 0.f);
    float  s0 = 0.f, s1 = 0.f;

    const uint2* pl = (const uint2*)(g_xlh + (size_t)g_csr[beg] * (DIM / 2));
    uint2 nu0 = pl[lane], nu1 = pl[lane + 32];

    for (int e = beg; e < end; e++) {
        float4 l0 = u2f4(nu0), l1 = u2f4(nu1);
        if (e + 1 < end) {
            const uint2* pn = (const uint2*)(g_xlh + (size_t)g_csr[e + 1] * (DIM / 2));
            nu0 = pn[lane]; nu1 = pn[lane + 32];
        }

        float sl = dot4_lrelu(a0, l0, r0);
        float sh = dot4_lrelu(a1, l1, r1);
#pragma unroll
        for (int off = 4; off; off >>= 1) {
            sl += __shfl_xor_sync(0xffffffffu, sl, off);
            sh += __shfl_xor_sync(0xffffffffu, sh, off);
        }
        float ex = 0.f;
        if (sub < 2) ex = __expf(sub == 0 ? sl : sh);
        float exl = __shfl_sync(0xffffffffu, ex, grp * 8);
        float exh = __shfl_sync(0xffffffffu, ex, grp * 8 + 1);

        acc0.x += exl * l0.x; acc0.y += exl * l0.y;
        acc0.z += exl * l0.z; acc0.w += exl * l0.w;
        acc1.x += exh * l1.x; acc1.y += exh * l1.y;
        acc1.z += exh * l1.z; acc1.w += exh * l1.w;
        s0 += exl; s1 += exh;
    }

    float inv0 = 1.f / s0, inv1 = 1.f / s1;
    const float4* pb = (const float4*)bias;
    float4 b0 = pb[lane], b1 = pb[lane + 32];

    float4 v0 = make_float4(acc0.x * inv0 + b0.x, acc0.y * inv0 + b0.y,
                            acc0.z * inv0 + b0.z, acc0.w * inv0 + b0.w);
    float4 v1 = make_float4(acc1.x * inv1 + b1.x, acc1.y * inv1 + b1.y,
                            acc1.z * inv1 + b1.z, acc1.w * inv1 + b1.w);

    float* dst = (mode == 0) ? g_h : outp;
    if (mode == 0) {   // ELU -> layer-2 GEMM input
        v0.x = v0.x > 0.f ? v0.x : expm1f(v0.x);
        v0.y = v0.y > 0.f ? v0.y : expm1f(v0.y);
        v0.z = v0.z > 0.f ? v0.z : expm1f(v0.z);
        v0.w = v0.w > 0.f ? v0.w : expm1f(v0.w);
        v1.x = v1.x > 0.f ? v1.x : expm1f(v1.x);
        v1.y = v1.y > 0.f ? v1.y : expm1f(v1.y);
        v1.z = v1.z > 0.f ? v1.z : expm1f(v1.z);
        v1.w = v1.w > 0.f ? v1.w : expm1f(v1.w);
    }
    float4* po = (float4*)(dst + (size_t)node * DIM);
    po[lane]      = v0;
    po[lane + 32] = v1;
}

// ---------------- host entry ----------------
extern "C" void kernel_launch(void* const* d_in, const int* in_sizes, int n_in,
                              void* d_out, int out_size) {
    const float* x    = (const float*)d_in[0];
    const void*  eidx = d_in[1];
    const float* Wl1  = (const float*)d_in[2];
    const float* Wr1  = (const float*)d_in[3];
    const float* att1 = (const float*)d_in[4];
    const float* b1   = (const float*)d_in[5];
    const float* Wl2  = (const float*)d_in[6];
    const float* Wr2  = (const float*)d_in[7];
    const float* att2 = (const float*)d_in[8];
    const float* b2   = (const float*)d_in[9];
    float*       outp = (float*)d_out;

    dim3 ggemm((N_NODES + TBM - 1) / TBM, DIM / TBN, 2);
    dim3 gnode((N_NODES + WPB - 1) / WPB);

    // ---- CSR build (once, reused by both layers) ----
    detect_kernel  <<<1, 1>>>((const int*)eidx);
    deg_init_kernel<<<NBLK, 256>>>();
    hist_kernel    <<<(N_EDGES + 255) / 256, 256>>>(eidx);
    scan1_kernel   <<<NBLK, 256>>>();
    scan2_kernel   <<<1, 256>>>();
    scan3_kernel   <<<NBLK, 256>>>();
    scatter_kernel <<<(EP + 255) / 256, 256>>>(eidx);

    // ---- layer 1 ----
    gemm_f16_kernel<<<ggemm, 256>>>(x, Wl1, Wr1, 0);
    gat_node_kernel<<<gnode, WPB * 32>>>(att1, b1, outp, 0);

    // ---- layer 2 ----
    gemm_f16_kernel<<<ggemm, 256>>>(x, Wl2, Wr2, 1);
    gat_node_kernel<<<gnode, WPB * 32>>>(att2, b2, outp, 1);
}

// round 13
// speedup vs baseline: 1.2877x; 1.0087x over previous
#include <cuda_runtime.h>
#include <cuda_fp16.h>
#include <stdint.h>
#include <math.h>

#define N_NODES 50000
#define N_EDGES 800000
#define EP      (N_EDGES + N_NODES)   // edges incl. self-loops = 850000
#define DIM     256
#define NH      8
#define NBLK    ((N_NODES + 255) / 256)   // 196 scan blocks

// ---------------- static device scratch (no allocs allowed) ----------------
__device__ __align__(16) unsigned g_xlh[(size_t)N_NODES * DIM / 2]; // x@Wl, half2
__device__ __align__(16) float    g_xr [(size_t)N_NODES * DIM];    // x@Wr, fp32
__device__ __align__(16) float    g_h  [(size_t)N_NODES * DIM];    // layer-1 out (fp32)
__device__ int g_deg [N_NODES];
__device__ int g_roff[N_NODES + 1];
__device__ int g_cur [N_NODES];
__device__ int g_csr [EP];
__device__ int g_part[256];
__device__ int g_pofs[256];
__device__ int g_is64;

__device__ __forceinline__ unsigned h2u(float a, float b) {
    __half2 h = __floats2half2_rn(a, b);
    return *(unsigned*)&h;
}

__device__ __forceinline__ int load_idx(const void* e, size_t i) {
    return g_is64 ? (int)((const long long*)e)[i] : ((const int*)e)[i];
}

// ---------------- prep: deg=1 + edge dtype detection (merged) --------------
__global__ void prep_kernel(const int* __restrict__ e) {
    int i = blockIdx.x * blockDim.x + threadIdx.x;
    if (i < N_NODES) g_deg[i] = 1;
    if (i == 0) {
        int zeros = 0;
#pragma unroll
        for (int j = 1; j < 128; j += 2) zeros += (e[j] == 0);
        g_is64 = (zeros >= 32);
    }
}

__global__ void hist_kernel(const void* __restrict__ eidx) {
    int e = blockIdx.x * blockDim.x + threadIdx.x;
    if (e < N_EDGES) atomicAdd(&g_deg[load_idx(eidx, (size_t)N_EDGES + e)], 1);
}

__global__ void scan1_kernel() {
    __shared__ int sh[256];
    int t = threadIdx.x;
    int i = blockIdx.x * 256 + t;
    int v = (i < N_NODES) ? g_deg[i] : 0;
    sh[t] = v;
    __syncthreads();
#pragma unroll
    for (int off = 1; off < 256; off <<= 1) {
        int u = (t >= off) ? sh[t - off] : 0;
        __syncthreads();
        sh[t] += u;
        __syncthreads();
    }
    if (i < N_NODES) g_roff[i] = sh[t] - v;
    if (t == 255) g_part[blockIdx.x] = sh[255];
}

__global__ void scan2_kernel() {
    __shared__ int sh[256];
    int t = threadIdx.x;
    int v = (t < NBLK) ? g_part[t] : 0;
    sh[t] = v;
    __syncthreads();
#pragma unroll
    for (int off = 1; off < 256; off <<= 1) {
        int u = (t >= off) ? sh[t - off] : 0;
        __syncthreads();
        sh[t] += u;
        __syncthreads();
    }
    g_pofs[t] = sh[t] - v;
}

__global__ void scan3_kernel() {
    int i = blockIdx.x * 256 + threadIdx.x;
    if (i < N_NODES) {
        int val = g_roff[i] + g_pofs[blockIdx.x];
        g_roff[i] = val;
        g_cur[i]  = val;
    }
    if (i == 0) g_roff[N_NODES] = EP;
}

__global__ void scatter_kernel(const void* __restrict__ eidx) {
    int e = blockIdx.x * blockDim.x + threadIdx.x;
    if (e >= EP) return;
    int src, dst;
    if (e < N_EDGES) { src = load_idx(eidx, e); dst = load_idx(eidx, (size_t)N_EDGES + e); }
    else             { src = e - N_EDGES;       dst = src; }
    int pos = atomicAdd(&g_cur[dst], 1);
    g_csr[pos] = src;
}

// ---------------- fp16 tensor-core GEMM (R11, unchanged) -------------------
#define TBM 128
#define TBN 128
#define TBK 32
#define XH_STRIDE 20
#define WH_STRIDE 136
#define XH_SZ (TBM * XH_STRIDE)
#define WH_SZ ((TBK / 2) * WH_STRIDE)

__device__ __forceinline__ void mma_f16(float* d,
                                        unsigned a0, unsigned a1,
                                        unsigned a2, unsigned a3,
                                        unsigned b0, unsigned b1) {
    asm volatile(
        "mma.sync.aligned.m16n8k16.row.col.f32.f16.f16.f32 "
        "{%0,%1,%2,%3}, {%4,%5,%6,%7}, {%8,%9}, {%0,%1,%2,%3};"
        : "+f"(d[0]), "+f"(d[1]), "+f"(d[2]), "+f"(d[3])
        : "r"(a0), "r"(a1), "r"(a2), "r"(a3), "r"(b0), "r"(b1));
}

__global__ __launch_bounds__(256, 2)
void gemm_f16_kernel(const float* __restrict__ Xin,
                     const float* __restrict__ Wl,
                     const float* __restrict__ Wr,
                     int use_h) {
    __shared__ unsigned Xs2[2][XH_SZ];
    __shared__ unsigned Ws2[2][WH_SZ];

    const float* X = use_h ? g_h : Xin;
    const float* W = (blockIdx.z == 0) ? Wl : Wr;

    int m0 = blockIdx.x * TBM;
    int n0 = blockIdx.y * TBN;
    int tid = threadIdx.x;
    int wid = tid >> 5, lane = tid & 31;
    int warp_m = wid & 1;
    int warp_n = wid >> 1;
    int g4 = lane >> 2;
    int t4 = lane & 3;

    int xrow[4], xk4[4];
    int wkp[2], wn4[2];
#pragma unroll
    for (int t = 0; t < 4; t++) {
        int f = tid + t * 256;
        xrow[t] = f >> 3;  xk4[t] = (f & 7) << 2;
    }
#pragma unroll
    for (int t = 0; t < 2; t++) {
        int idx = tid + t * 256;
        wkp[t] = idx >> 5;  wn4[t] = (idx & 31) << 2;
    }

    float4 xv[4], wva[2], wvb[2];

    auto load_tile = [&](int k0) {
#pragma unroll
        for (int t = 0; t < 4; t++) {
            int gr = m0 + xrow[t];
            xv[t] = make_float4(0.f, 0.f, 0.f, 0.f);
            if (gr < N_NODES)
                xv[t] = *(const float4*)(X + (size_t)gr * DIM + k0 + xk4[t]);
        }
#pragma unroll
        for (int t = 0; t < 2; t++) {
            int kr = k0 + 2 * wkp[t];
            wva[t] = *(const float4*)(W + (size_t)kr       * DIM + n0 + wn4[t]);
            wvb[t] = *(const float4*)(W + (size_t)(kr + 1) * DIM + n0 + wn4[t]);
        }
    };

    auto store_tile = [&](int p) {
        unsigned* Xs = Xs2[p];
        unsigned* Ws = Ws2[p];
#pragma unroll
        for (int t = 0; t < 4; t++) {
            uint2 u;
            u.x = h2u(xv[t].x, xv[t].y);
            u.y = h2u(xv[t].z, xv[t].w);
            *(uint2*)&Xs[xrow[t] * XH_STRIDE + (xk4[t] >> 1)] = u;
        }
#pragma unroll
        for (int t = 0; t < 2; t++) {
            uint4 u;
            u.x = h2u(wva[t].x, wvb[t].x);
            u.y = h2u(wva[t].y, wvb[t].y);
            u.z = h2u(wva[t].z, wvb[t].z);
            u.w = h2u(wva[t].w, wvb[t].w);
            *(uint4*)&Ws[wkp[t] * WH_STRIDE + wn4[t]] = u;
        }
    };

    float acc[4][4][4];
#pragma unroll
    for (int mt = 0; mt < 4; mt++)
#pragma unroll
        for (int nt = 0; nt < 4; nt++)
#pragma unroll
            for (int r = 0; r < 4; r++) acc[mt][nt][r] = 0.f;

    load_tile(0);
    store_tile(0);
    __syncthreads();
    load_tile(TBK);

    int p = 0;
    for (int k0 = 0; k0 < DIM; k0 += TBK) {
        unsigned* Xs = Xs2[p];
        unsigned* Ws = Ws2[p];

#pragma unroll
        for (int ks = 0; ks < 2; ks++) {
            unsigned b[4][2];
#pragma unroll
            for (int nt = 0; nt < 4; nt++) {
                int col = warp_n * 32 + nt * 8 + g4;
                b[nt][0] = Ws[(ks * 8 +     t4) * WH_STRIDE + col];
                b[nt][1] = Ws[(ks * 8 + 4 + t4) * WH_STRIDE + col];
            }
#pragma unroll
            for (int mt = 0; mt < 4; mt++) {
                int row = warp_m * 64 + mt * 16 + g4;
                unsigned a0 = Xs[ row      * XH_STRIDE + ks * 8 +     t4];
                unsigned a1 = Xs[(row + 8) * XH_STRIDE + ks * 8 +     t4];
                unsigned a2 = Xs[ row      * XH_STRIDE + ks * 8 + 4 + t4];
                unsigned a3 = Xs[(row + 8) * XH_STRIDE + ks * 8 + 4 + t4];
#pragma unroll
                for (int nt = 0; nt < 4; nt++)
                    mma_f16(acc[mt][nt], a0, a1, a2, a3, b[nt][0], b[nt][1]);
            }
        }

        if (k0 + TBK < DIM) {
            store_tile(1 - p);
            if (k0 + 2 * TBK < DIM) load_tile(k0 + 2 * TBK);
            __syncthreads();
        }
        p ^= 1;
    }

    if (blockIdx.z == 0) {
#pragma unroll
        for (int mt = 0; mt < 4; mt++) {
            int r0 = m0 + warp_m * 64 + mt * 16 + g4;
#pragma unroll
            for (int nt = 0; nt < 4; nt++) {
                int c = n0 + warp_n * 32 + nt * 8 + t4 * 2;
                if (r0 < N_NODES)
                    g_xlh[((size_t)r0 * DIM + c) >> 1] =
                        h2u(acc[mt][nt][0], acc[mt][nt][1]);
                if (r0 + 8 < N_NODES)
                    g_xlh[((size_t)(r0 + 8) * DIM + c) >> 1] =
                        h2u(acc[mt][nt][2], acc[mt][nt][3]);
            }
        }
    } else {
#pragma unroll
        for (int mt = 0; mt < 4; mt++) {
            int r0 = m0 + warp_m * 64 + mt * 16 + g4;
#pragma unroll
            for (int nt = 0; nt < 4; nt++) {
                int c = n0 + warp_n * 32 + nt * 8 + t4 * 2;
                if (r0 < N_NODES)
                    *(float2*)(g_xr + (size_t)r0 * DIM + c) =
                        make_float2(acc[mt][nt][0], acc[mt][nt][1]);
                if (r0 + 8 < N_NODES)
                    *(float2*)(g_xr + (size_t)(r0 + 8) * DIM + c) =
                        make_float2(acc[mt][nt][2], acc[mt][nt][3]);
            }
        }
    }
}

// ---------------- fused GATv2 node kernel (warp/node, 2-deep prefetch) -----
__device__ __forceinline__ float dot4_lrelu(float4 a, float4 l, float4 r) {
    float z, s;
    z = l.x + r.x; z = z > 0.f ? z : 0.2f * z; s  = a.x * z;
    z = l.y + r.y; z = z > 0.f ? z : 0.2f * z; s += a.y * z;
    z = l.z + r.z; z = z > 0.f ? z : 0.2f * z; s += a.z * z;
    z = l.w + r.w; z = z > 0.f ? z : 0.2f * z; s += a.w * z;
    return s;
}

__device__ __forceinline__ float4 u2f4(uint2 u) {
    float2 lo = __half22float2(*(__half2*)&u.x);
    float2 hi = __half22float2(*(__half2*)&u.y);
    return make_float4(lo.x, lo.y, hi.x, hi.y);
}

#define WPB 8   // warps per block

__global__ __launch_bounds__(WPB * 32)
void gat_node_kernel(const float* __restrict__ att,
                     const float* __restrict__ bias,
                     float* __restrict__ outp, int mode) {
    int node = blockIdx.x * WPB + (threadIdx.x >> 5);
    if (node >= N_NODES) return;
    int lane = threadIdx.x & 31;
    int grp  = lane >> 3;
    int sub  = lane & 7;

    const float4* pa = (const float4*)att;
    float4 a0 = pa[lane], a1 = pa[lane + 32];
    const float4* pr = (const float4*)(g_xr + (size_t)node * DIM);
    float4 r0 = pr[lane], r1 = pr[lane + 32];

    int beg = g_roff[node], end = g_roff[node + 1];

    float4 acc0 = make_float4(0.f, 0.f, 0.f, 0.f);
    float4 acc1 = make_float4(0.f, 0.f, 0.f, 0.f);
    float  s0 = 0.f, s1 = 0.f;

    auto proc = [&](uint2 u0, uint2 u1) {
        float4 l0 = u2f4(u0), l1 = u2f4(u1);
        float sl = dot4_lrelu(a0, l0, r0);
        float sh = dot4_lrelu(a1, l1, r1);
#pragma unroll
        for (int off = 4; off; off >>= 1) {
            sl += __shfl_xor_sync(0xffffffffu, sl, off);
            sh += __shfl_xor_sync(0xffffffffu, sh, off);
        }
        float ex = 0.f;
        if (sub < 2) ex = __expf(sub == 0 ? sl : sh);
        float exl = __shfl_sync(0xffffffffu, ex, grp * 8);
        float exh = __shfl_sync(0xffffffffu, ex, grp * 8 + 1);
        acc0.x += exl * l0.x; acc0.y += exl * l0.y;
        acc0.z += exl * l0.z; acc0.w += exl * l0.w;
        acc1.x += exh * l1.x; acc1.y += exh * l1.y;
        acc1.z += exh * l1.z; acc1.w += exh * l1.w;
        s0 += exl; s1 += exh;
    };

    // 2-deep software pipeline over the CSR edge list
    uint2 c00, c01, c10, c11;
    c10 = c11 = make_uint2(0u, 0u);
    {
        const uint2* p = (const uint2*)(g_xlh + (size_t)g_csr[beg] * (DIM / 2));
        c00 = p[lane]; c01 = p[lane + 32];
    }
    if (beg + 1 < end) {
        const uint2* p = (const uint2*)(g_xlh + (size_t)g_csr[beg + 1] * (DIM / 2));
        c10 = p[lane]; c11 = p[lane + 32];
    }

    for (int e = beg; e < end; e += 2) {
        uint2 n00 = make_uint2(0u, 0u), n01 = n00, n10 = n00, n11 = n00;
        if (e + 2 < end) {
            const uint2* p = (const uint2*)(g_xlh + (size_t)g_csr[e + 2] * (DIM / 2));
            n00 = p[lane]; n01 = p[lane + 32];
        }
        if (e + 3 < end) {
            const uint2* p = (const uint2*)(g_xlh + (size_t)g_csr[e + 3] * (DIM / 2));
            n10 = p[lane]; n11 = p[lane + 32];
        }

        proc(c00, c01);
        if (e + 1 < end) proc(c10, c11);

        c00 = n00; c01 = n01; c10 = n10; c11 = n11;
    }

    float inv0 = 1.f / s0, inv1 = 1.f / s1;
    const float4* pb = (const float4*)bias;
    float4 b0 = pb[lane], b1 = pb[lane + 32];

    float4 v0 = make_float4(acc0.x * inv0 + b0.x, acc0.y * inv0 + b0.y,
                            acc0.z * inv0 + b0.z, acc0.w * inv0 + b0.w);
    float4 v1 = make_float4(acc1.x * inv1 + b1.x, acc1.y * inv1 + b1.y,
                            acc1.z * inv1 + b1.z, acc1.w * inv1 + b1.w);

    float* dst = (mode == 0) ? g_h : outp;
    if (mode == 0) {   // ELU -> layer-2 GEMM input
        v0.x = v0.x > 0.f ? v0.x : expm1f(v0.x);
        v0.y = v0.y > 0.f ? v0.y : expm1f(v0.y);
        v0.z = v0.z > 0.f ? v0.z : expm1f(v0.z);
        v0.w = v0.w > 0.f ? v0.w : expm1f(v0.w);
        v1.x = v1.x > 0.f ? v1.x : expm1f(v1.x);
        v1.y = v1.y > 0.f ? v1.y : expm1f(v1.y);
        v1.z = v1.z > 0.f ? v1.z : expm1f(v1.z);
        v1.w = v1.w > 0.f ? v1.w : expm1f(v1.w);
    }
    float4* po = (float4*)(dst + (size_t)node * DIM);
    po[lane]      = v0;
    po[lane + 32] = v1;
}

// ---------------- host entry ----------------
extern "C" void kernel_launch(void* const* d_in, const int* in_sizes, int n_in,
                              void* d_out, int out_size) {
    const float* x    = (const float*)d_in[0];
    const void*  eidx = d_in[1];
    const float* Wl1  = (const float*)d_in[2];
    const float* Wr1  = (const float*)d_in[3];
    const float* att1 = (const float*)d_in[4];
    const float* b1   = (const float*)d_in[5];
    const float* Wl2  = (const float*)d_in[6];
    const float* Wr2  = (const float*)d_in[7];
    const float* att2 = (const float*)d_in[8];
    const float* b2   = (const float*)d_in[9];
    float*       outp = (float*)d_out;

    dim3 ggemm((N_NODES + TBM - 1) / TBM, DIM / TBN, 2);
    dim3 gnode((N_NODES + WPB - 1) / WPB);

    // ---- CSR build (once, reused by both layers) ----
    prep_kernel    <<<NBLK, 256>>>((const int*)eidx);
    hist_kernel    <<<(N_EDGES + 255) / 256, 256>>>(eidx);
    scan1_kernel   <<<NBLK, 256>>>();
    scan2_kernel   <<<1, 256>>>();
    scan3_kernel   <<<NBLK, 256>>>();
    scatter_kernel <<<(EP + 255) / 256, 256>>>(eidx);

    // ---- layer 1 ----
    gemm_f16_kernel<<<ggemm, 256>>>(x, Wl1, Wr1, 0);
    gat_node_kernel<<<gnode, WPB * 32>>>(att1, b1, outp, 0);

    // ---- layer 2 ----
    gemm_f16_kernel<<<ggemm, 256>>>(x, Wl2, Wr2, 1);
    gat_node_kernel<<<gnode, WPB * 32>>>(att2, b2, outp, 1);
}

// round 14
// speedup vs baseline: 1.3068x; 1.0148x over previous
#include <cuda_runtime.h>
#include <cuda_fp16.h>
#include <stdint.h>
#include <math.h>

#define N_NODES 50000
#define N_EDGES 800000
#define EP      (N_EDGES + N_NODES)   // edges incl. self-loops = 850000
#define DIM     256
#define NH      8
#define NBLK    ((N_NODES + 255) / 256)   // 196 scan blocks

// ---------------- static device scratch (no allocs allowed) ----------------
__device__ __align__(16) unsigned g_xlh[(size_t)N_NODES * DIM / 2]; // x@Wl, half2
__device__ __align__(16) float    g_xr [(size_t)N_NODES * DIM];    // x@Wr, fp32
__device__ __align__(16) unsigned g_hh [(size_t)N_NODES * DIM / 2]; // layer-1 out, half2
__device__ __align__(16) unsigned g_wt [4 * DIM * DIM / 2];        // W^T fp16 [mat][n][k]
__device__ int g_deg [N_NODES];
__device__ int g_roff[N_NODES + 1];
__device__ int g_cur [N_NODES];
__device__ int g_csr [EP];
__device__ int g_part[256];
__device__ int g_is64;

__device__ __forceinline__ unsigned h2u(float a, float b) {
    __half2 h = __floats2half2_rn(a, b);
    return *(unsigned*)&h;
}

__device__ __forceinline__ int load_idx(const void* e, size_t i) {
    return g_is64 ? (int)((const long long*)e)[i] : ((const int*)e)[i];
}

// ---------------- prep: deg=1 + edge dtype detection (merged) --------------
__global__ void prep_kernel(const int* __restrict__ e) {
    int i = blockIdx.x * blockDim.x + threadIdx.x;
    if (i < N_NODES) g_deg[i] = 1;
    if (i == 0) {
        int zeros = 0;
#pragma unroll
        for (int j = 1; j < 128; j += 2) zeros += (e[j] == 0);
        g_is64 = (zeros >= 32);
    }
}

// ---------------- W transpose + fp16 convert (once) ----------------
// g_wt[m][n*128 + kw] = half2{ W_m[2kw][n], W_m[2kw+1][n] }  (k-contiguous per n)
__global__ void convwt_kernel(const float* __restrict__ Wl1, const float* __restrict__ Wr1,
                              const float* __restrict__ Wl2, const float* __restrict__ Wr2) {
    int i = blockIdx.x * 256 + threadIdx.x;   // 32768 words per matrix
    int m = blockIdx.y;
    const float* W = (m == 0) ? Wl1 : (m == 1) ? Wr1 : (m == 2) ? Wl2 : Wr2;
    int n  = i >> 7;
    int kw = i & 127;
    int k  = kw * 2;
    g_wt[m * (DIM * DIM / 2) + i] = h2u(W[(size_t)k * DIM + n], W[(size_t)(k + 1) * DIM + n]);
}

__global__ void hist_kernel(const void* __restrict__ eidx) {
    int e = blockIdx.x * blockDim.x + threadIdx.x;
    if (e < N_EDGES) atomicAdd(&g_deg[load_idx(eidx, (size_t)N_EDGES + e)], 1);
}

__global__ void scan1_kernel() {
    __shared__ int sh[256];
    int t = threadIdx.x;
    int i = blockIdx.x * 256 + t;
    int v = (i < N_NODES) ? g_deg[i] : 0;
    sh[t] = v;
    __syncthreads();
#pragma unroll
    for (int off = 1; off < 256; off <<= 1) {
        int u = (t >= off) ? sh[t - off] : 0;
        __syncthreads();
        sh[t] += u;
        __syncthreads();
    }
    if (i < N_NODES) g_roff[i] = sh[t] - v;
    if (t == 255) g_part[blockIdx.x] = sh[255];
}

// scan3: each block locally scans block totals, adds its prefix (scan2 merged)
__global__ void scan3_kernel() {
    __shared__ int sh[256];
    int t = threadIdx.x;
    sh[t] = (t < NBLK) ? g_part[t] : 0;
    __syncthreads();
#pragma unroll
    for (int off = 1; off < 256; off <<= 1) {
        int u = (t >= off) ? sh[t - off] : 0;
        __syncthreads();
        sh[t] += u;
        __syncthreads();
    }
    int pofs = (blockIdx.x > 0) ? sh[blockIdx.x - 1] : 0;
    int i = blockIdx.x * 256 + t;
    if (i < N_NODES) {
        int val = g_roff[i] + pofs;
        g_roff[i] = val;
        g_cur[i]  = val;
    }
    if (i == 0) g_roff[N_NODES] = EP;
}

__global__ void scatter_kernel(const void* __restrict__ eidx) {
    int e = blockIdx.x * blockDim.x + threadIdx.x;
    if (e >= EP) return;
    int src, dst;
    if (e < N_EDGES) { src = load_idx(eidx, e); dst = load_idx(eidx, (size_t)N_EDGES + e); }
    else             { src = e - N_EDGES;       dst = src; }
    int pos = atomicAdd(&g_cur[dst], 1);
    g_csr[pos] = src;
}

// ---------------- fp16 tensor-core GEMM with ldmatrix fragment loads -------
// A and B tiles both [row][k] fp16, stride 20 words (80 B, 16B-aligned,
// conflict-free LDSM phases). A = X rows; B = W^T rows (n-major, k-contig).
#define TBM 128
#define TBN 128
#define TBK 32
#define ST  20                 // words per tile row
#define TILE_SZ (128 * ST)     // 2560 words

__device__ __forceinline__ void mma_f16(float* d,
                                        unsigned a0, unsigned a1,
                                        unsigned a2, unsigned a3,
                                        unsigned b0, unsigned b1) {
    asm volatile(
        "mma.sync.aligned.m16n8k16.row.col.f32.f16.f16.f32 "
        "{%0,%1,%2,%3}, {%4,%5,%6,%7}, {%8,%9}, {%0,%1,%2,%3};"
        : "+f"(d[0]), "+f"(d[1]), "+f"(d[2]), "+f"(d[3])
        : "r"(a0), "r"(a1), "r"(a2), "r"(a3), "r"(b0), "r"(b1));
}

__device__ __forceinline__ void ldsm_x4(unsigned& a0, unsigned& a1,
                                        unsigned& a2, unsigned& a3, uint32_t addr) {
    asm volatile("ldmatrix.sync.aligned.m8n8.x4.shared.b16 {%0,%1,%2,%3}, [%4];"
                 : "=r"(a0), "=r"(a1), "=r"(a2), "=r"(a3) : "r"(addr));
}
__device__ __forceinline__ void ldsm_x2(unsigned& b0, unsigned& b1, uint32_t addr) {
    asm volatile("ldmatrix.sync.aligned.m8n8.x2.shared.b16 {%0,%1}, [%2];"
                 : "=r"(b0), "=r"(b1) : "r"(addr));
}

__global__ __launch_bounds__(256, 2)
void gemm_f16_kernel(const float* __restrict__ Xin, int layer) {
    __shared__ __align__(16) unsigned As2[2][TILE_SZ];
    __shared__ __align__(16) unsigned Bs2[2][TILE_SZ];

    int m0 = blockIdx.x * TBM;
    int n0 = blockIdx.y * TBN;
    int mat = layer * 2 + blockIdx.z;
    const unsigned* WT = g_wt + (size_t)mat * (DIM * DIM / 2);

    int tid = threadIdx.x;
    int wid = tid >> 5, lane = tid & 31;
    int warp_m = wid & 1;
    int warp_n = wid >> 1;
    int g4 = lane >> 2;
    int t4 = lane & 3;

    // staging index precompute
    int xrow[4], xk4[4];   // layer-0 A (fp32 source): 4 float4/thread
    int hrow[2], hc[2];    // half source (g_hh A, g_wt B): 2 uint4/thread
#pragma unroll
    for (int t = 0; t < 4; t++) {
        int f = tid + t * 256;
        xrow[t] = f >> 3;  xk4[t] = (f & 7) << 2;
    }
#pragma unroll
    for (int t = 0; t < 2; t++) {
        int f = tid + t * 256;
        hrow[t] = f >> 2;  hc[t] = (f & 3) << 2;   // 4-word chunk index
    }

    float4 xv[4];      // staged fp32 A values (layer 0)
    uint4  hv[2];      // staged half A values (layer 1)
    uint4  wv[2];      // staged B values

    auto load_tile = [&](int k0) {
        int kw = k0 >> 1;   // word offset along k
        if (layer == 0) {
#pragma unroll
            for (int t = 0; t < 4; t++) {
                int gr = m0 + xrow[t];
                xv[t] = make_float4(0.f, 0.f, 0.f, 0.f);
                if (gr < N_NODES)
                    xv[t] = *(const float4*)(Xin + (size_t)gr * DIM + k0 + xk4[t]);
            }
        } else {
#pragma unroll
            for (int t = 0; t < 2; t++) {
                int gr = m0 + hrow[t];
                hv[t] = make_uint4(0u, 0u, 0u, 0u);
                if (gr < N_NODES)
                    hv[t] = *(const uint4*)(g_hh + (size_t)gr * (DIM / 2) + kw + hc[t]);
            }
        }
#pragma unroll
        for (int t = 0; t < 2; t++)
            wv[t] = *(const uint4*)(WT + (size_t)(n0 + hrow[t]) * (DIM / 2) + kw + hc[t]);
    };

    auto store_tile = [&](int p) {
        unsigned* As = As2[p];
        unsigned* Bs = Bs2[p];
        if (layer == 0) {
#pragma unroll
            for (int t = 0; t < 4; t++) {
                uint2 u;
                u.x = h2u(xv[t].x, xv[t].y);
                u.y = h2u(xv[t].z, xv[t].w);
                *(uint2*)&As[xrow[t] * ST + (xk4[t] >> 1)] = u;
            }
        } else {
#pragma unroll
            for (int t = 0; t < 2; t++)
                *(uint4*)&As[hrow[t] * ST + hc[t]] = hv[t];
        }
#pragma unroll
        for (int t = 0; t < 2; t++)
            *(uint4*)&Bs[hrow[t] * ST + hc[t]] = wv[t];
    };

    float acc[4][4][4];
#pragma unroll
    for (int mt = 0; mt < 4; mt++)
#pragma unroll
        for (int nt = 0; nt < 4; nt++)
#pragma unroll
            for (int r = 0; r < 4; r++) acc[mt][nt][r] = 0.f;

    load_tile(0);
    store_tile(0);
    __syncthreads();
    load_tile(TBK);

    // ldmatrix lane base addresses (byte offsets within a tile)
    uint32_t a_lane_off = (uint32_t)(((warp_m * 64 + (lane & 15)) * ST + (lane >> 4) * 4) * 4);
    uint32_t b_lane_off = (uint32_t)(((warp_n * 32 + (lane & 7)) * ST + ((lane >> 3) & 1) * 4) * 4);

    int p = 0;
    for (int k0 = 0; k0 < DIM; k0 += TBK) {
        uint32_t sa = (uint32_t)__cvta_generic_to_shared(As2[p]) + a_lane_off;
        uint32_t sbb = (uint32_t)__cvta_generic_to_shared(Bs2[p]) + b_lane_off;

#pragma unroll
        for (int ks = 0; ks < 2; ks++) {
            unsigned b[4][2];
#pragma unroll
            for (int nt = 0; nt < 4; nt++)
                ldsm_x2(b[nt][0], b[nt][1], sbb + (uint32_t)((nt * 8 * ST + ks * 8) * 4));
#pragma unroll
            for (int mt = 0; mt < 4; mt++) {
                unsigned a0, a1, a2, a3;
                ldsm_x4(a0, a1, a2, a3, sa + (uint32_t)((mt * 16 * ST + ks * 8) * 4));
#pragma unroll
                for (int nt = 0; nt < 4; nt++)
                    mma_f16(acc[mt][nt], a0, a1, a2, a3, b[nt][0], b[nt][1]);
            }
        }

        if (k0 + TBK < DIM) {
            store_tile(1 - p);
            if (k0 + 2 * TBK < DIM) load_tile(k0 + 2 * TBK);
            __syncthreads();
        }
        p ^= 1;
    }

    if (blockIdx.z == 0) {
#pragma unroll
        for (int mt = 0; mt < 4; mt++) {
            int r0 = m0 + warp_m * 64 + mt * 16 + g4;
#pragma unroll
            for (int nt = 0; nt < 4; nt++) {
                int c = n0 + warp_n * 32 + nt * 8 + t4 * 2;
                if (r0 < N_NODES)
                    g_xlh[((size_t)r0 * DIM + c) >> 1] =
                        h2u(acc[mt][nt][0], acc[mt][nt][1]);
                if (r0 + 8 < N_NODES)
                    g_xlh[((size_t)(r0 + 8) * DIM + c) >> 1] =
                        h2u(acc[mt][nt][2], acc[mt][nt][3]);
            }
        }
    } else {
#pragma unroll
        for (int mt = 0; mt < 4; mt++) {
            int r0 = m0 + warp_m * 64 + mt * 16 + g4;
#pragma unroll
            for (int nt = 0; nt < 4; nt++) {
                int c = n0 + warp_n * 32 + nt * 8 + t4 * 2;
                if (r0 < N_NODES)
                    *(float2*)(g_xr + (size_t)r0 * DIM + c) =
                        make_float2(acc[mt][nt][0], acc[mt][nt][1]);
                if (r0 + 8 < N_NODES)
                    *(float2*)(g_xr + (size_t)(r0 + 8) * DIM + c) =
                        make_float2(acc[mt][nt][2], acc[mt][nt][3]);
            }
        }
    }
}

// ---------------- fused GATv2 node kernel (warp/node, 2-deep prefetch) -----
__device__ __forceinline__ float dot4_lrelu(float4 a, float4 l, float4 r) {
    float z, s;
    z = l.x + r.x; z = z > 0.f ? z : 0.2f * z; s  = a.x * z;
    z = l.y + r.y; z = z > 0.f ? z : 0.2f * z; s += a.y * z;
    z = l.z + r.z; z = z > 0.f ? z : 0.2f * z; s += a.z * z;
    z = l.w + r.w; z = z > 0.f ? z : 0.2f * z; s += a.w * z;
    return s;
}

__device__ __forceinline__ float4 u2f4(uint2 u) {
    float2 lo = __half22float2(*(__half2*)&u.x);
    float2 hi = __half22float2(*(__half2*)&u.y);
    return make_float4(lo.x, lo.y, hi.x, hi.y);
}

#define WPB 8   // warps per block

__global__ __launch_bounds__(WPB * 32)
void gat_node_kernel(const float* __restrict__ att,
                     const float* __restrict__ bias,
                     float* __restrict__ outp, int mode) {
    int node = blockIdx.x * WPB + (threadIdx.x >> 5);
    if (node >= N_NODES) return;
    int lane = threadIdx.x & 31;
    int grp  = lane >> 3;
    int sub  = lane & 7;

    const float4* pa = (const float4*)att;
    float4 a0 = pa[lane], a1 = pa[lane + 32];
    const float4* pr = (const float4*)(g_xr + (size_t)node * DIM);
    float4 r0 = pr[lane], r1 = pr[lane + 32];

    int beg = g_roff[node], end = g_roff[node + 1];

    float4 acc0 = make_float4(0.f, 0.f, 0.f, 0.f);
    float4 acc1 = make_float4(0.f, 0.f, 0.f, 0.f);
    float  s0 = 0.f, s1 = 0.f;

    auto proc = [&](uint2 u0, uint2 u1) {
        float4 l0 = u2f4(u0), l1 = u2f4(u1);
        float sl = dot4_lrelu(a0, l0, r0);
        float sh = dot4_lrelu(a1, l1, r1);
#pragma unroll
        for (int off = 4; off; off >>= 1) {
            sl += __shfl_xor_sync(0xffffffffu, sl, off);
            sh += __shfl_xor_sync(0xffffffffu, sh, off);
        }
        float ex = 0.f;
        if (sub < 2) ex = __expf(sub == 0 ? sl : sh);
        float exl = __shfl_sync(0xffffffffu, ex, grp * 8);
        float exh = __shfl_sync(0xffffffffu, ex, grp * 8 + 1);
        acc0.x += exl * l0.x; acc0.y += exl * l0.y;
        acc0.z += exl * l0.z; acc0.w += exl * l0.w;
        acc1.x += exh * l1.x; acc1.y += exh * l1.y;
        acc1.z += exh * l1.z; acc1.w += exh * l1.w;
        s0 += exl; s1 += exh;
    };

    uint2 c00, c01, c10, c11;
    c10 = c11 = make_uint2(0u, 0u);
    {
        const uint2* p = (const uint2*)(g_xlh + (size_t)g_csr[beg] * (DIM / 2));
        c00 = p[lane]; c01 = p[lane + 32];
    }
    if (beg + 1 < end) {
        const uint2* p = (const uint2*)(g_xlh + (size_t)g_csr[beg + 1] * (DIM / 2));
        c10 = p[lane]; c11 = p[lane + 32];
    }

    for (int e = beg; e < end; e += 2) {
        uint2 n00 = make_uint2(0u, 0u), n01 = n00, n10 = n00, n11 = n00;
        if (e + 2 < end) {
            const uint2* p = (const uint2*)(g_xlh + (size_t)g_csr[e + 2] * (DIM / 2));
            n00 = p[lane]; n01 = p[lane + 32];
        }
        if (e + 3 < end) {
            const uint2* p = (const uint2*)(g_xlh + (size_t)g_csr[e + 3] * (DIM / 2));
            n10 = p[lane]; n11 = p[lane + 32];
        }

        proc(c00, c01);
        if (e + 1 < end) proc(c10, c11);

        c00 = n00; c01 = n01; c10 = n10; c11 = n11;
    }

    float inv0 = 1.f / s0, inv1 = 1.f / s1;
    const float4* pb = (const float4*)bias;
    float4 b0 = pb[lane], b1 = pb[lane + 32];

    float4 v0 = make_float4(acc0.x * inv0 + b0.x, acc0.y * inv0 + b0.y,
                            acc0.z * inv0 + b0.z, acc0.w * inv0 + b0.w);
    float4 v1 = make_float4(acc1.x * inv1 + b1.x, acc1.y * inv1 + b1.y,
                            acc1.z * inv1 + b1.z, acc1.w * inv1 + b1.w);

    if (mode == 0) {   // ELU -> half2-packed layer-2 input (same RN as staging did)
        v0.x = v0.x > 0.f ? v0.x : expm1f(v0.x);
        v0.y = v0.y > 0.f ? v0.y : expm1f(v0.y);
        v0.z = v0.z > 0.f ? v0.z : expm1f(v0.z);
        v0.w = v0.w > 0.f ? v0.w : expm1f(v0.w);
        v1.x = v1.x > 0.f ? v1.x : expm1f(v1.x);
        v1.y = v1.y > 0.f ? v1.y : expm1f(v1.y);
        v1.z = v1.z > 0.f ? v1.z : expm1f(v1.z);
        v1.w = v1.w > 0.f ? v1.w : expm1f(v1.w);
        uint2* ph = (uint2*)(g_hh + (size_t)node * (DIM / 2));
        ph[lane]      = make_uint2(h2u(v0.x, v0.y), h2u(v0.z, v0.w));
        ph[lane + 32] = make_uint2(h2u(v1.x, v1.y), h2u(v1.z, v1.w));
    } else {
        float4* po = (float4*)(outp + (size_t)node * DIM);
        po[lane]      = v0;
        po[lane + 32] = v1;
    }
}

// ---------------- host entry ----------------
extern "C" void kernel_launch(void* const* d_in, const int* in_sizes, int n_in,
                              void* d_out, int out_size) {
    const float* x    = (const float*)d_in[0];
    const void*  eidx = d_in[1];
    const float* Wl1  = (const float*)d_in[2];
    const float* Wr1  = (const float*)d_in[3];
    const float* att1 = (const float*)d_in[4];
    const float* b1   = (const float*)d_in[5];
    const float* Wl2  = (const float*)d_in[6];
    const float* Wr2  = (const float*)d_in[7];
    const float* att2 = (const float*)d_in[8];
    const float* b2   = (const float*)d_in[9];
    float*       outp = (float*)d_out;

    dim3 ggemm((N_NODES + TBM - 1) / TBM, DIM / TBN, 2);
    dim3 gnode((N_NODES + WPB - 1) / WPB);

    // ---- one-time prep: W transpose + CSR build ----
    prep_kernel    <<<NBLK, 256>>>((const int*)eidx);
    convwt_kernel  <<<dim3(128, 4), 256>>>(Wl1, Wr1, Wl2, Wr2);
    hist_kernel    <<<(N_EDGES + 255) / 256, 256>>>(eidx);
    scan1_kernel   <<<NBLK, 256>>>();
    scan3_kernel   <<<NBLK, 256>>>();
    scatter_kernel <<<(EP + 255) / 256, 256>>>(eidx);

    // ---- layer 1 ----
    gemm_f16_kernel<<<ggemm, 256>>>(x, 0);
    gat_node_kernel<<<gnode, WPB * 32>>>(att1, b1, outp, 0);

    // ---- layer 2 ----
    gemm_f16_kernel<<<ggemm, 256>>>(x, 1);
    gat_node_kernel<<<gnode, WPB * 32>>>(att2, b2, outp, 1);
}

// round 15
// speedup vs baseline: 1.3156x; 1.0068x over previous
#include <cuda_runtime.h>
#include <cuda_fp16.h>
#include <stdint.h>
#include <math.h>

#define N_NODES 50000
#define N_EDGES 800000
#define EP      (N_EDGES + N_NODES)   // edges incl. self-loops = 850000
#define DIM     256
#define NH      8
#define NBLK    ((N_NODES + 255) / 256)   // 196 scan blocks

// ---------------- static device scratch (no allocs allowed) ----------------
__device__ __align__(16) unsigned g_xlh[(size_t)N_NODES * DIM / 2]; // x@Wl, half2
__device__ __align__(16) unsigned g_xrh[(size_t)N_NODES * DIM / 2]; // x@Wr, half2
__device__ __align__(16) unsigned g_hh [(size_t)N_NODES * DIM / 2]; // layer-1 out, half2
__device__ __align__(16) unsigned g_wt [4 * DIM * DIM / 2];        // W^T fp16 [mat][n][k]
__device__ int g_deg [N_NODES];        // statically zero; re-zeroed in scan3 each call
__device__ int g_roff[N_NODES + 1];
__device__ int g_cur [N_NODES];
__device__ int g_csr [EP];
__device__ int g_part[256];
__device__ int g_is64;

__device__ __forceinline__ unsigned h2u(float a, float b) {
    __half2 h = __floats2half2_rn(a, b);
    return *(unsigned*)&h;
}

__device__ __forceinline__ int load_idx(const void* e, size_t i) {
    return g_is64 ? (int)((const long long*)e)[i] : ((const int*)e)[i];
}

// ---------------- edge dtype detection ----------------
__global__ void detect_kernel(const int* __restrict__ e) {
    int zeros = 0;
#pragma unroll
    for (int j = 1; j < 128; j += 2) zeros += (e[j] == 0);
    g_is64 = (zeros >= 32);
}

// ---------------- W transpose + fp16 convert (once per call) ---------------
__global__ void convwt_kernel(const float* __restrict__ Wl1, const float* __restrict__ Wr1,
                              const float* __restrict__ Wl2, const float* __restrict__ Wr2) {
    int i = blockIdx.x * 256 + threadIdx.x;   // 32768 words per matrix
    int m = blockIdx.y;
    const float* W = (m == 0) ? Wl1 : (m == 1) ? Wr1 : (m == 2) ? Wl2 : Wr2;
    int n  = i >> 7;
    int kw = i & 127;
    int k  = kw * 2;
    g_wt[m * (DIM * DIM / 2) + i] = h2u(W[(size_t)k * DIM + n], W[(size_t)(k + 1) * DIM + n]);
}

// ---------------- CSR build (deg counts real edges only; self-loops implicit)
__global__ void hist_kernel(const void* __restrict__ eidx) {
    int e = blockIdx.x * blockDim.x + threadIdx.x;
    if (e < N_EDGES) atomicAdd(&g_deg[load_idx(eidx, (size_t)N_EDGES + e)], 1);
}

__global__ void scan1_kernel() {
    __shared__ int sh[256];
    int t = threadIdx.x;
    int i = blockIdx.x * 256 + t;
    int v = (i < N_NODES) ? g_deg[i] : 0;
    sh[t] = v;
    __syncthreads();
#pragma unroll
    for (int off = 1; off < 256; off <<= 1) {
        int u = (t >= off) ? sh[t - off] : 0;
        __syncthreads();
        sh[t] += u;
        __syncthreads();
    }
    if (i < N_NODES) g_roff[i] = sh[t] - v;   // block-local exclusive prefix
    if (t == 255) g_part[blockIdx.x] = sh[255];
}

// scan3: adds block prefix + i (self-loop slots), writes self-loop into csr,
// inits cursor past it, and re-zeroes g_deg for the next graph replay.
__global__ void scan3_kernel() {
    __shared__ int sh[256];
    int t = threadIdx.x;
    sh[t] = (t < NBLK) ? g_part[t] : 0;
    __syncthreads();
#pragma unroll
    for (int off = 1; off < 256; off <<= 1) {
        int u = (t >= off) ? sh[t - off] : 0;
        __syncthreads();
        sh[t] += u;
        __syncthreads();
    }
    int pofs = (blockIdx.x > 0) ? sh[blockIdx.x - 1] : 0;
    int i = blockIdx.x * 256 + t;
    if (i < N_NODES) {
        int val = g_roff[i] + pofs + i;   // +i: one self-loop slot per preceding node
        g_roff[i]  = val;
        g_csr[val] = i;                   // self-loop first in each node's list
        g_cur[i]   = val + 1;
        g_deg[i]   = 0;                   // reset for next replay (scan1 already read it)
    }
    if (i == 0) g_roff[N_NODES] = EP;
}

__global__ void scatter_kernel(const void* __restrict__ eidx) {
    int e = blockIdx.x * blockDim.x + threadIdx.x;
    if (e >= N_EDGES) return;
    int src = load_idx(eidx, e);
    int dst = load_idx(eidx, (size_t)N_EDGES + e);
    int pos = atomicAdd(&g_cur[dst], 1);
    g_csr[pos] = src;
}

// ---------------- fp16 tensor-core GEMM with ldmatrix fragment loads -------
#define TBM 128
#define TBN 128
#define TBK 32
#define ST  20                 // words per tile row
#define TILE_SZ (128 * ST)

__device__ __forceinline__ void mma_f16(float* d,
                                        unsigned a0, unsigned a1,
                                        unsigned a2, unsigned a3,
                                        unsigned b0, unsigned b1) {
    asm volatile(
        "mma.sync.aligned.m16n8k16.row.col.f32.f16.f16.f32 "
        "{%0,%1,%2,%3}, {%4,%5,%6,%7}, {%8,%9}, {%0,%1,%2,%3};"
        : "+f"(d[0]), "+f"(d[1]), "+f"(d[2]), "+f"(d[3])
        : "r"(a0), "r"(a1), "r"(a2), "r"(a3), "r"(b0), "r"(b1));
}

__device__ __forceinline__ void ldsm_x4(unsigned& a0, unsigned& a1,
                                        unsigned& a2, unsigned& a3, uint32_t addr) {
    asm volatile("ldmatrix.sync.aligned.m8n8.x4.shared.b16 {%0,%1,%2,%3}, [%4];"
                 : "=r"(a0), "=r"(a1), "=r"(a2), "=r"(a3) : "r"(addr));
}
__device__ __forceinline__ void ldsm_x2(unsigned& b0, unsigned& b1, uint32_t addr) {
    asm volatile("ldmatrix.sync.aligned.m8n8.x2.shared.b16 {%0,%1}, [%2];"
                 : "=r"(b0), "=r"(b1) : "r"(addr));
}

__global__ __launch_bounds__(256, 2)
void gemm_f16_kernel(const float* __restrict__ Xin, int layer) {
    __shared__ __align__(16) unsigned As2[2][TILE_SZ];
    __shared__ __align__(16) unsigned Bs2[2][TILE_SZ];

    int m0 = blockIdx.x * TBM;
    int n0 = blockIdx.y * TBN;
    int mat = layer * 2 + blockIdx.z;
    const unsigned* WT = g_wt + (size_t)mat * (DIM * DIM / 2);

    int tid = threadIdx.x;
    int wid = tid >> 5, lane = tid & 31;
    int warp_m = wid & 1;
    int warp_n = wid >> 1;
    int g4 = lane >> 2;
    int t4 = lane & 3;

    int xrow[4], xk4[4];
    int hrow[2], hc[2];
#pragma unroll
    for (int t = 0; t < 4; t++) {
        int f = tid + t * 256;
        xrow[t] = f >> 3;  xk4[t] = (f & 7) << 2;
    }
#pragma unroll
    for (int t = 0; t < 2; t++) {
        int f = tid + t * 256;
        hrow[t] = f >> 2;  hc[t] = (f & 3) << 2;
    }

    float4 xv[4];
    uint4  hv[2];
    uint4  wv[2];

    auto load_tile = [&](int k0) {
        int kw = k0 >> 1;
        if (layer == 0) {
#pragma unroll
            for (int t = 0; t < 4; t++) {
                int gr = m0 + xrow[t];
                xv[t] = make_float4(0.f, 0.f, 0.f, 0.f);
                if (gr < N_NODES)
                    xv[t] = *(const float4*)(Xin + (size_t)gr * DIM + k0 + xk4[t]);
            }
        } else {
#pragma unroll
            for (int t = 0; t < 2; t++) {
                int gr = m0 + hrow[t];
                hv[t] = make_uint4(0u, 0u, 0u, 0u);
                if (gr < N_NODES)
                    hv[t] = *(const uint4*)(g_hh + (size_t)gr * (DIM / 2) + kw + hc[t]);
            }
        }
#pragma unroll
        for (int t = 0; t < 2; t++)
            wv[t] = *(const uint4*)(WT + (size_t)(n0 + hrow[t]) * (DIM / 2) + kw + hc[t]);
    };

    auto store_tile = [&](int p) {
        unsigned* As = As2[p];
        unsigned* Bs = Bs2[p];
        if (layer == 0) {
#pragma unroll
            for (int t = 0; t < 4; t++) {
                uint2 u;
                u.x = h2u(xv[t].x, xv[t].y);
                u.y = h2u(xv[t].z, xv[t].w);
                *(uint2*)&As[xrow[t] * ST + (xk4[t] >> 1)] = u;
            }
        } else {
#pragma unroll
            for (int t = 0; t < 2; t++)
                *(uint4*)&As[hrow[t] * ST + hc[t]] = hv[t];
        }
#pragma unroll
        for (int t = 0; t < 2; t++)
            *(uint4*)&Bs[hrow[t] * ST + hc[t]] = wv[t];
    };

    float acc[4][4][4];
#pragma unroll
    for (int mt = 0; mt < 4; mt++)
#pragma unroll
        for (int nt = 0; nt < 4; nt++)
#pragma unroll
            for (int r = 0; r < 4; r++) acc[mt][nt][r] = 0.f;

    load_tile(0);
    store_tile(0);
    __syncthreads();
    load_tile(TBK);

    uint32_t a_lane_off = (uint32_t)(((warp_m * 64 + (lane & 15)) * ST + (lane >> 4) * 4) * 4);
    uint32_t b_lane_off = (uint32_t)(((warp_n * 32 + (lane & 7)) * ST + ((lane >> 3) & 1) * 4) * 4);

    int p = 0;
    for (int k0 = 0; k0 < DIM; k0 += TBK) {
        uint32_t sa  = (uint32_t)__cvta_generic_to_shared(As2[p]) + a_lane_off;
        uint32_t sbb = (uint32_t)__cvta_generic_to_shared(Bs2[p]) + b_lane_off;

#pragma unroll
        for (int ks = 0; ks < 2; ks++) {
            unsigned b[4][2];
#pragma unroll
            for (int nt = 0; nt < 4; nt++)
                ldsm_x2(b[nt][0], b[nt][1], sbb + (uint32_t)((nt * 8 * ST + ks * 8) * 4));
#pragma unroll
            for (int mt = 0; mt < 4; mt++) {
                unsigned a0, a1, a2, a3;
                ldsm_x4(a0, a1, a2, a3, sa + (uint32_t)((mt * 16 * ST + ks * 8) * 4));
#pragma unroll
                for (int nt = 0; nt < 4; nt++)
                    mma_f16(acc[mt][nt], a0, a1, a2, a3, b[nt][0], b[nt][1]);
            }
        }

        if (k0 + TBK < DIM) {
            store_tile(1 - p);
            if (k0 + 2 * TBK < DIM) load_tile(k0 + 2 * TBK);
            __syncthreads();
        }
        p ^= 1;
    }

    unsigned* Cout = (blockIdx.z == 0) ? g_xlh : g_xrh;
#pragma unroll
    for (int mt = 0; mt < 4; mt++) {
        int r0 = m0 + warp_m * 64 + mt * 16 + g4;
#pragma unroll
        for (int nt = 0; nt < 4; nt++) {
            int c = n0 + warp_n * 32 + nt * 8 + t4 * 2;
            if (r0 < N_NODES)
                Cout[((size_t)r0 * DIM + c) >> 1] =
                    h2u(acc[mt][nt][0], acc[mt][nt][1]);
            if (r0 + 8 < N_NODES)
                Cout[((size_t)(r0 + 8) * DIM + c) >> 1] =
                    h2u(acc[mt][nt][2], acc[mt][nt][3]);
        }
    }
}

// ---------------- fused GATv2 node kernel (warp/node, 2-deep prefetch) -----
__device__ __forceinline__ float dot4_lrelu(float4 a, float4 l, float4 r) {
    float z, s;
    z = l.x + r.x; z = z > 0.f ? z : 0.2f * z; s  = a.x * z;
    z = l.y + r.y; z = z > 0.f ? z : 0.2f * z; s += a.y * z;
    z = l.z + r.z; z = z > 0.f ? z : 0.2f * z; s += a.z * z;
    z = l.w + r.w; z = z > 0.f ? z : 0.2f * z; s += a.w * z;
    return s;
}

__device__ __forceinline__ float4 u2f4(uint2 u) {
    float2 lo = __half22float2(*(__half2*)&u.x);
    float2 hi = __half22float2(*(__half2*)&u.y);
    return make_float4(lo.x, lo.y, hi.x, hi.y);
}

#define WPB 8   // warps per block

__global__ __launch_bounds__(WPB * 32)
void gat_node_kernel(const float* __restrict__ att,
                     const float* __restrict__ bias,
                     float* __restrict__ outp, int mode) {
    int node = blockIdx.x * WPB + (threadIdx.x >> 5);
    if (node >= N_NODES) return;
    int lane = threadIdx.x & 31;
    int grp  = lane >> 3;
    int sub  = lane & 7;

    const float4* pa = (const float4*)att;
    float4 a0 = pa[lane], a1 = pa[lane + 32];
    const uint2* prh = (const uint2*)(g_xrh + (size_t)node * (DIM / 2));
    float4 r0 = u2f4(prh[lane]), r1 = u2f4(prh[lane + 32]);

    int beg = g_roff[node], end = g_roff[node + 1];

    float4 acc0 = make_float4(0.f, 0.f, 0.f, 0.f);
    float4 acc1 = make_float4(0.f, 0.f, 0.f, 0.f);
    float  s0 = 0.f, s1 = 0.f;

    auto proc = [&](uint2 u0, uint2 u1) {
        float4 l0 = u2f4(u0), l1 = u2f4(u1);
        float sl = dot4_lrelu(a0, l0, r0);
        float sh = dot4_lrelu(a1, l1, r1);
#pragma unroll
        for (int off = 4; off; off >>= 1) {
            sl += __shfl_xor_sync(0xffffffffu, sl, off);
            sh += __shfl_xor_sync(0xffffffffu, sh, off);
        }
        float ex = 0.f;
        if (sub < 2) ex = __expf(sub == 0 ? sl : sh);
        float exl = __shfl_sync(0xffffffffu, ex, grp * 8);
        float exh = __shfl_sync(0xffffffffu, ex, grp * 8 + 1);
        acc0.x += exl * l0.x; acc0.y += exl * l0.y;
        acc0.z += exl * l0.z; acc0.w += exl * l0.w;
        acc1.x += exh * l1.x; acc1.y += exh * l1.y;
        acc1.z += exh * l1.z; acc1.w += exh * l1.w;
        s0 += exl; s1 += exh;
    };

    uint2 c00, c01, c10, c11;
    c10 = c11 = make_uint2(0u, 0u);
    {
        const uint2* p = (const uint2*)(g_xlh + (size_t)g_csr[beg] * (DIM / 2));
        c00 = p[lane]; c01 = p[lane + 32];
    }
    if (beg + 1 < end) {
        const uint2* p = (const uint2*)(g_xlh + (size_t)g_csr[beg + 1] * (DIM / 2));
        c10 = p[lane]; c11 = p[lane + 32];
    }

    for (int e = beg; e < end; e += 2) {
        uint2 n00 = make_uint2(0u, 0u), n01 = n00, n10 = n00, n11 = n00;
        if (e + 2 < end) {
            const uint2* p = (const uint2*)(g_xlh + (size_t)g_csr[e + 2] * (DIM / 2));
            n00 = p[lane]; n01 = p[lane + 32];
        }
        if (e + 3 < end) {
            const uint2* p = (const uint2*)(g_xlh + (size_t)g_csr[e + 3] * (DIM / 2));
            n10 = p[lane]; n11 = p[lane + 32];
        }

        proc(c00, c01);
        if (e + 1 < end) proc(c10, c11);

        c00 = n00; c01 = n01; c10 = n10; c11 = n11;
    }

    float inv0 = 1.f / s0, inv1 = 1.f / s1;
    const float4* pb = (const float4*)bias;
    float4 b0 = pb[lane], b1 = pb[lane + 32];

    float4 v0 = make_float4(acc0.x * inv0 + b0.x, acc0.y * inv0 + b0.y,
                            acc0.z * inv0 + b0.z, acc0.w * inv0 + b0.w);
    float4 v1 = make_float4(acc1.x * inv1 + b1.x, acc1.y * inv1 + b1.y,
                            acc1.z * inv1 + b1.z, acc1.w * inv1 + b1.w);

    if (mode == 0) {   // ELU -> half2-packed layer-2 input
        v0.x = v0.x > 0.f ? v0.x : expm1f(v0.x);
        v0.y = v0.y > 0.f ? v0.y : expm1f(v0.y);
        v0.z = v0.z > 0.f ? v0.z : expm1f(v0.z);
        v0.w = v0.w > 0.f ? v0.w : expm1f(v0.w);
        v1.x = v1.x > 0.f ? v1.x : expm1f(v1.x);
        v1.y = v1.y > 0.f ? v1.y : expm1f(v1.y);
        v1.z = v1.z > 0.f ? v1.z : expm1f(v1.z);
        v1.w = v1.w > 0.f ? v1.w : expm1f(v1.w);
        uint2* ph = (uint2*)(g_hh + (size_t)node * (DIM / 2));
        ph[lane]      = make_uint2(h2u(v0.x, v0.y), h2u(v0.z, v0.w));
        ph[lane + 32] = make_uint2(h2u(v1.x, v1.y), h2u(v1.z, v1.w));
    } else {
        float4* po = (float4*)(outp + (size_t)node * DIM);
        po[lane]      = v0;
        po[lane + 32] = v1;
    }
}

// ---------------- host entry ----------------
extern "C" void kernel_launch(void* const* d_in, const int* in_sizes, int n_in,
                              void* d_out, int out_size) {
    const float* x    = (const float*)d_in[0];
    const void*  eidx = d_in[1];
    const float* Wl1  = (const float*)d_in[2];
    const float* Wr1  = (const float*)d_in[3];
    const float* att1 = (const float*)d_in[4];
    const float* b1   = (const float*)d_in[5];
    const float* Wl2  = (const float*)d_in[6];
    const float* Wr2  = (const float*)d_in[7];
    const float* att2 = (const float*)d_in[8];
    const float* b2   = (const float*)d_in[9];
    float*       outp = (float*)d_out;

    dim3 ggemm((N_NODES + TBM - 1) / TBM, DIM / TBN, 2);
    dim3 gnode((N_NODES + WPB - 1) / WPB);

    // ---- one-time prep: W transpose + CSR build (5 launches) ----
    detect_kernel  <<<1, 1>>>((const int*)eidx);
    convwt_kernel  <<<dim3(128, 4), 256>>>(Wl1, Wr1, Wl2, Wr2);
    hist_kernel    <<<(N_EDGES + 255) / 256, 256>>>(eidx);
    scan1_kernel   <<<NBLK, 256>>>();
    scan3_kernel   <<<NBLK, 256>>>();
    scatter_kernel <<<(N_EDGES + 255) / 256, 256>>>(eidx);

    // ---- layer 1 ----
    gemm_f16_kernel<<<ggemm, 256>>>(x, 0);
    gat_node_kernel<<<gnode, WPB * 32>>>(att1, b1, outp, 0);

    // ---- layer 2 ----
    gemm_f16_kernel<<<ggemm, 256>>>(x, 1);
    gat_node_kernel<<<gnode, WPB * 32>>>(att2, b2, outp, 1);
}